// round 10
// baseline (speedup 1.0000x reference)
#include <cuda_runtime.h>
#include <cstddef>

#define B_  8
#define C_  64
#define N_  4096
#define N4_ 1024

// Scratch (static device globals).
__device__ float g_K [B_*C_*N_];   // (b,c,n)  keys   stage1, channel-major
__device__ float g_V [B_*N_*C_];   // (b,n,c)  values stage1, position-major
__device__ float g_Q [B_*C_*N_];   // (b,c,n)  queries stage2, channel-major
__device__ float g_qp[B_*C_*N4_];  // (b,c,j)  pooled queries stage1, channel-major
__device__ float g_o1[B_*N4_*C_];  // (b,j,c)  stage1 output, position-major
__device__ float g_kp[B_*C_*N4_];  // (b,c,j)  keys   stage2, channel-major
__device__ float g_vp[B_*N4_*C_];  // (b,j,c)  values stage2, position-major
// Split-K stage1 partials.
__device__ float g_po[2*B_*N4_*C_]; // [half][b][j][c] unnormalized acc
__device__ float g_m2[2*B_*N4_];
__device__ float g_l2[2*B_*N4_];

typedef unsigned long long u64;

__device__ __forceinline__ u64 pack2(float x, float y) {
    u64 r; asm("mov.b64 %0, {%1,%2};" : "=l"(r) : "f"(x), "f"(y)); return r;
}
__device__ __forceinline__ float2 unpk(u64 v) {
    float2 r; asm("mov.b64 {%0,%1}, %2;" : "=f"(r.x), "=f"(r.y) : "l"(v)); return r;
}
__device__ __forceinline__ void fma2(u64& d, u64 a, u64 b) {
    asm("fma.rn.f32x2 %0, %1, %2, %0;" : "+l"(d) : "l"(a), "l"(b));
}
__device__ __forceinline__ void mul2(u64& d, u64 a) {
    asm("mul.rn.f32x2 %0, %0, %1;" : "+l"(d) : "l"(a));
}

union F4U { float4 v; float f[4]; u64 u[2]; };

// ================= Projection GEMM (64x64 W @ 64x64 X tile) ================
#define PW 136
#define PX 68
#define PROJ_SMEM_FLOATS (64*PW + 64*PX + 64)

__device__ __forceinline__ void load_w_dup(const float* __restrict__ w,
                                           const float* __restrict__ bias,
                                           float* sWTd, float* sb, int tid)
{
    for (int i = tid; i < 4096; i += 256) {
        int o = i >> 6, c = i & 63;
        float v = w[i];
        sWTd[c * PW + 2 * o]     = v;
        sWTd[c * PW + 2 * o + 1] = v;
    }
    if (tid < 64) sb[tid] = bias[tid];
}

__device__ __forceinline__ void gemm_tile(const float* sWTd, const float* sX,
                                          const float* sb, u64 acc2[4][2],
                                          int tx, int ty)
{
    #pragma unroll
    for (int i = 0; i < 4; i++) {
        float b = sb[4 * ty + i];
        u64 bb = pack2(b, b);
        acc2[i][0] = bb; acc2[i][1] = bb;
    }
    #pragma unroll 4
    for (int k = 0; k < 64; k++) {
        F4U wa, wb, x;
        wa.v = *(const float4*)(sWTd + k * PW + 8 * ty);
        wb.v = *(const float4*)(sWTd + k * PW + 8 * ty + 4);
        x.v  = *(const float4*)(sX + k * PX + 4 * tx);
        fma2(acc2[0][0], wa.u[0], x.u[0]); fma2(acc2[0][1], wa.u[0], x.u[1]);
        fma2(acc2[1][0], wa.u[1], x.u[0]); fma2(acc2[1][1], wa.u[1], x.u[1]);
        fma2(acc2[2][0], wb.u[0], x.u[0]); fma2(acc2[2][1], wb.u[0], x.u[1]);
        fma2(acc2[3][0], wb.u[1], x.u[0]); fma2(acc2[3][1], wb.u[1], x.u[1]);
    }
}

__device__ __forceinline__ void store_cmajor(float* __restrict__ dst, int nstride,
                                             u64 acc2[4][2], int tx, int ty)
{
    #pragma unroll
    for (int i = 0; i < 4; i++) {
        float2 a0 = unpk(acc2[i][0]), a1 = unpk(acc2[i][1]);
        *(float4*)(dst + (size_t)(4 * ty + i) * nstride + 4 * tx) =
            make_float4(a0.x, a0.y, a1.x, a1.y);
    }
}

__device__ __forceinline__ void store_nmajor(float* __restrict__ dst,
                                             u64 acc2[4][2], int tx, int ty)
{
    float2 r[4][2];
    #pragma unroll
    for (int i = 0; i < 4; i++) {
        r[i][0] = unpk(acc2[i][0]); r[i][1] = unpk(acc2[i][1]);
    }
    #pragma unroll
    for (int jj = 0; jj < 4; jj++) {
        float v0 = (jj & 1) ? r[0][jj >> 1].y : r[0][jj >> 1].x;
        float v1 = (jj & 1) ? r[1][jj >> 1].y : r[1][jj >> 1].x;
        float v2 = (jj & 1) ? r[2][jj >> 1].y : r[2][jj >> 1].x;
        float v3 = (jj & 1) ? r[3][jj >> 1].y : r[3][jj >> 1].x;
        *(float4*)(dst + (size_t)(4 * tx + jj) * 64 + 4 * ty) =
            make_float4(v0, v1, v2, v3);
    }
}

__global__ __launch_bounds__(256, 2)
void projA_kernel(const float* __restrict__ x,
                  const float* __restrict__ wK, const float* __restrict__ bK,
                  const float* __restrict__ wV, const float* __restrict__ bV,
                  const float* __restrict__ wQ, const float* __restrict__ bQ)
{
    extern __shared__ float sh[];
    float* sWTd = sh;
    float* sX   = sh + 64 * PW;
    float* sb   = sX + 64 * PX;
    int which = blockIdx.y;
    int tid = threadIdx.x;
    const float* w  = which == 0 ? wK : (which == 1 ? wV : wQ);
    const float* bs = which == 0 ? bK : (which == 1 ? bV : bQ);
    load_w_dup(w, bs, sWTd, sb, tid);

    int gpos0 = blockIdx.x * 64;
    int b = gpos0 >> 12, n0 = gpos0 & (N_ - 1);
    const float* xb = x + (size_t)b * C_ * N_;
    for (int i = tid; i < 1024; i += 256) {
        int c = i >> 4, pg = (i & 15) * 4;
        *(float4*)(sX + c * PX + pg) = *(const float4*)(xb + (size_t)c * N_ + n0 + pg);
    }
    __syncthreads();

    int tx = tid & 15, ty = tid >> 4;
    u64 acc2[4][2];
    gemm_tile(sWTd, sX, sb, acc2, tx, ty);

    if (which == 0)      store_cmajor(g_K + (size_t)b * C_ * N_ + n0, N_, acc2, tx, ty);
    else if (which == 2) store_cmajor(g_Q + (size_t)b * C_ * N_ + n0, N_, acc2, tx, ty);
    else                 store_nmajor(g_V + (size_t)gpos0 * 64, acc2, tx, ty);
}

__global__ __launch_bounds__(256, 2)
void projP_kernel(const float* __restrict__ x,
                  const float* __restrict__ wq, const float* __restrict__ bq)
{
    extern __shared__ float sh[];
    float* sWTd = sh;
    float* sX   = sh + 64 * PW;
    float* sb   = sX + 64 * PX;
    int tid = threadIdx.x;
    load_w_dup(wq, bq, sWTd, sb, tid);

    int gpos0 = blockIdx.x * 64;
    int b = gpos0 >> 10, j0 = gpos0 & (N4_ - 1);
    const float* xb = x + (size_t)b * C_ * N_;
    for (int i = tid; i < 4096; i += 256) {
        int c = i >> 6, j = i & 63;
        int jj = j0 + j;
        int r = jj >> 5, col = jj & 31;
        const float* p = xb + (size_t)c * N_ + r * 128 + col * 2;
        float2 a = *(const float2*)p;
        float2 d = *(const float2*)(p + 64);
        sX[c * PX + j] = 0.25f * (a.x + a.y + d.x + d.y);
    }
    __syncthreads();

    int tx = tid & 15, ty = tid >> 4;
    u64 acc2[4][2];
    gemm_tile(sWTd, sX, sb, acc2, tx, ty);
    store_cmajor(g_qp + (size_t)b * C_ * N4_ + j0, N4_, acc2, tx, ty);
}

__global__ __launch_bounds__(256, 2)
void projC_kernel(const float* __restrict__ wk, const float* __restrict__ bk,
                  const float* __restrict__ wv, const float* __restrict__ bv)
{
    extern __shared__ float sh[];
    float* sWTd = sh;
    float* sX   = sh + 64 * PW;
    float* sb   = sX + 64 * PX;
    int which = blockIdx.y;
    int tid = threadIdx.x;
    load_w_dup(which ? wv : wk, which ? bv : bk, sWTd, sb, tid);

    int gpos0 = blockIdx.x * 64;
    int b = gpos0 >> 10, j0 = gpos0 & (N4_ - 1);
    const float* src = g_o1 + (size_t)gpos0 * 64;
    for (int i = tid; i < 1024; i += 256) {
        int pos = i >> 4, cg = (i & 15) * 4;
        float4 v = *(const float4*)(src + (size_t)pos * 64 + cg);
        sX[(cg + 0) * PX + pos] = v.x;
        sX[(cg + 1) * PX + pos] = v.y;
        sX[(cg + 2) * PX + pos] = v.z;
        sX[(cg + 3) * PX + pos] = v.w;
    }
    __syncthreads();

    int tx = tid & 15, ty = tid >> 4;
    u64 acc2[4][2];
    gemm_tile(sWTd, sX, sb, acc2, tx, ty);
    if (which == 0) store_cmajor(g_kp + (size_t)b * C_ * N4_ + j0, N4_, acc2, tx, ty);
    else            store_nmajor(g_vp + (size_t)gpos0 * 64, acc2, tx, ty);
}

// ================= Fused flash-attention (fp32x2, dup-pair smem) ============
// 64-query tile per CTA, 256 threads as 16x16, 4x4 per thread.
// sQd [d][2q] dup pairs (pitch PP; broadcast LDS, built once per CTA)
// sK  [d][n]  (pitch PK)      sV [n][c] (pitch PK)
// sPd [q][2k] dup pairs (pitch PP; built in softmax, +1 STS.128/row)
// Hot loops have ZERO pack MOVs: S = 3 LDS + 8 FFMA2 / d-step (fma-bound),
// PV = 12 LDS + 32 FFMA2 / 4-key chunk (fma-bound).

template<bool FINAL>
__global__ __launch_bounds__(256, 2)
void attn_kernel(float* __restrict__ outg,
                 const float* __restrict__ xr,
                 const float* __restrict__ gp)
{
    constexpr int NKEY = FINAL ? 1024 : 4096;
    constexpr int NQ   = FINAL ? 4096 : 1024;
    constexpr int PP = 136;
    constexpr int PK = 68;

    extern __shared__ float sh[];
    float* sQd = sh;                 // 64*136
    float* sK  = sQd + 64 * PP;      // 64*68
    float* sV  = sK  + 64 * PK;      // 64*68
    float* sPd = sV  + 64 * PK;      // 64*136

    int tid = threadIdx.x;
    int tx = tid & 15, ty = tid >> 4;
    int b  = blockIdx.y;
    int qt = blockIdx.x;
    int half = FINAL ? 0 : blockIdx.z;

    const float* Qb = (FINAL ? g_Q  : g_qp) + (size_t)b * C_ * NQ;
    const float* Kb = (FINAL ? g_kp : g_K ) + (size_t)b * C_ * NKEY;
    const float* Vb = (FINAL ? g_vp : g_V ) + (size_t)b * NKEY * C_;

    // Q tile, duplicated pairs: sQd[d][2q,2q+1] = Q[d][q]
    for (int i = tid; i < 1024; i += 256) {
        int row = i >> 4, dg = (i & 15) * 4;
        float4 v = *(const float4*)(Qb + (size_t)row * NQ + qt * 64 + dg);
        *(float4*)(sQd + row * PP + 2 * dg)     = make_float4(v.x, v.x, v.y, v.y);
        *(float4*)(sQd + row * PP + 2 * dg + 4) = make_float4(v.z, v.z, v.w, v.w);
    }

    float m[4], l[4];
    u64 acc2[4][2];
    #pragma unroll
    for (int i = 0; i < 4; i++) {
        m[i] = -1e30f; l[i] = 0.f;
        acc2[i][0] = 0ull; acc2[i][1] = 0ull;
    }
    __syncthreads();

    int kt0 = FINAL ? 0 : half * (NKEY / 128);
    int kt1 = FINAL ? NKEY / 64 : kt0 + (NKEY / 128);
    for (int kt = kt0; kt < kt1; kt++) {
        for (int i = tid; i < 1024; i += 256) {
            int row = i >> 4, dg = (i & 15) * 4;
            *(float4*)(sK + row * PK + dg) =
                *(const float4*)(Kb + (size_t)row * NKEY + kt * 64 + dg);
            *(float4*)(sV + row * PK + dg) =
                *(const float4*)(Vb + ((size_t)kt * 64 + row) * 64 + dg);
        }
        __syncthreads();

        // S = Q^T K : 2 broadcast LDS.128 (Q dup) + 1 LDS.128 (K) + 8 FFMA2
        u64 s2[4][2];
        #pragma unroll
        for (int i = 0; i < 4; i++) { s2[i][0] = 0ull; s2[i][1] = 0ull; }

        #pragma unroll 2
        for (int d = 0; d < 64; d++) {
            F4U qa, qb, k;
            qa.v = *(const float4*)(sQd + d * PP + 8 * ty);
            qb.v = *(const float4*)(sQd + d * PP + 8 * ty + 4);
            k.v  = *(const float4*)(sK  + d * PK + 4 * tx);
            fma2(s2[0][0], qa.u[0], k.u[0]); fma2(s2[0][1], qa.u[0], k.u[1]);
            fma2(s2[1][0], qa.u[1], k.u[0]); fma2(s2[1][1], qa.u[1], k.u[1]);
            fma2(s2[2][0], qb.u[0], k.u[0]); fma2(s2[2][1], qb.u[0], k.u[1]);
            fma2(s2[3][0], qb.u[1], k.u[0]); fma2(s2[3][1], qb.u[1], k.u[1]);
        }

        // Online softmax; write dup'd P tile.
        #pragma unroll
        for (int i = 0; i < 4; i++) {
            float2 a = unpk(s2[i][0]), c = unpk(s2[i][1]);
            float tm = fmaxf(fmaxf(a.x, a.y), fmaxf(c.x, c.y));
            tm = fmaxf(tm, __shfl_xor_sync(0xffffffffu, tm, 1));
            tm = fmaxf(tm, __shfl_xor_sync(0xffffffffu, tm, 2));
            tm = fmaxf(tm, __shfl_xor_sync(0xffffffffu, tm, 4));
            tm = fmaxf(tm, __shfl_xor_sync(0xffffffffu, tm, 8));
            float mn = fmaxf(m[i], tm);
            float alpha = __expf(m[i] - mn);
            float p0 = __expf(a.x - mn), p1 = __expf(a.y - mn);
            float p2 = __expf(c.x - mn), p3 = __expf(c.y - mn);
            float ps = p0 + p1 + p2 + p3;
            ps += __shfl_xor_sync(0xffffffffu, ps, 1);
            ps += __shfl_xor_sync(0xffffffffu, ps, 2);
            ps += __shfl_xor_sync(0xffffffffu, ps, 4);
            ps += __shfl_xor_sync(0xffffffffu, ps, 8);
            l[i] = l[i] * alpha + ps;
            m[i] = mn;
            u64 al2 = pack2(alpha, alpha);
            mul2(acc2[i][0], al2);
            mul2(acc2[i][1], al2);
            *(float4*)(sPd + (4*ty + i) * PP + 8*tx)     = make_float4(p0, p0, p1, p1);
            *(float4*)(sPd + (4*ty + i) * PP + 8*tx + 4) = make_float4(p2, p2, p3, p3);
        }
        __syncthreads();

        // O += P @ V : 8 LDS (P dup) + 4 LDS (V) + 32 FFMA2 per 4-key chunk
        #pragma unroll 2
        for (int kk4 = 0; kk4 < 16; kk4++) {
            F4U pa[4], pb[4], vv[4];
            #pragma unroll
            for (int i = 0; i < 4; i++) {
                pa[i].v = *(const float4*)(sPd + (4*ty + i) * PP + 8*kk4);
                pb[i].v = *(const float4*)(sPd + (4*ty + i) * PP + 8*kk4 + 4);
            }
            #pragma unroll
            for (int t = 0; t < 4; t++)
                vv[t].v = *(const float4*)(sV + (4*kk4 + t) * PK + 4*tx);
            #pragma unroll
            for (int i = 0; i < 4; i++) {
                fma2(acc2[i][0], pa[i].u[0], vv[0].u[0]); fma2(acc2[i][1], pa[i].u[0], vv[0].u[1]);
                fma2(acc2[i][0], pa[i].u[1], vv[1].u[0]); fma2(acc2[i][1], pa[i].u[1], vv[1].u[1]);
                fma2(acc2[i][0], pb[i].u[0], vv[2].u[0]); fma2(acc2[i][1], pb[i].u[0], vv[2].u[1]);
                fma2(acc2[i][0], pb[i].u[1], vv[3].u[0]); fma2(acc2[i][1], pb[i].u[1], vv[3].u[1]);
            }
        }
        __syncthreads();
    }

    if (!FINAL) {
        // Split-K partial: unnormalized acc + (m,l) per row.
        size_t base = ((size_t)(half * B_ + b) * N4_ + qt * 64) * 64;
        #pragma unroll
        for (int i = 0; i < 4; i++) {
            float2 a = unpk(acc2[i][0]), c = unpk(acc2[i][1]);
            *(float4*)(g_po + base + (4*ty + i) * 64 + 4*tx) =
                make_float4(a.x, a.y, c.x, c.y);
        }
        if (tx == 0) {
            int r = (half * B_ + b) * N4_ + qt * 64 + 4 * ty;
            #pragma unroll
            for (int i = 0; i < 4; i++) { g_m2[r + i] = m[i]; g_l2[r + i] = l[i]; }
        }
    } else {
        #pragma unroll
        for (int i = 0; i < 4; i++) {
            float inv = 1.f / l[i];
            float2 a = unpk(acc2[i][0]), c = unpk(acc2[i][1]);
            *(float4*)(sPd + (4*ty + i) * PP + 4*tx) =
                make_float4(a.x * inv, a.y * inv, c.x * inv, c.y * inv);
        }
        __syncthreads();
        float gamma = gp[0];
        int n0 = qt * 64;
        #pragma unroll 4
        for (int r2 = 0; r2 < 16; r2++) {
            int idx = r2 * 256 + tid;
            int c = idx >> 6, nl = idx & 63;
            size_t ga = ((size_t)b * 64 + c) * (size_t)N_ + n0 + nl;
            outg[ga] = gamma * sPd[nl * PP + c] + xr[ga];
        }
    }
}

// Merge the two split-K partials: exact flash combine.
__global__ __launch_bounds__(256)
void combine_kernel()
{
    int idx = blockIdx.x * 256 + threadIdx.x;   // over 8192*16 float4 groups
    int row = idx >> 4, c4 = (idx & 15) * 4;
    float m0 = g_m2[row], m1 = g_m2[B_*N4_ + row];
    float l0 = g_l2[row], l1 = g_l2[B_*N4_ + row];
    float M = fmaxf(m0, m1);
    float w0 = __expf(m0 - M), w1 = __expf(m1 - M);
    float inv = 1.f / (l0 * w0 + l1 * w1);
    float4 a0 = *(const float4*)(g_po + (size_t)row * 64 + c4);
    float4 a1 = *(const float4*)(g_po + (size_t)(B_*N4_ + row) * 64 + c4);
    *(float4*)(g_o1 + (size_t)row * 64 + c4) = make_float4(
        (a0.x * w0 + a1.x * w1) * inv,
        (a0.y * w0 + a1.y * w1) * inv,
        (a0.z * w0 + a1.z * w1) * inv,
        (a0.w * w0 + a1.w * w1) * inv);
}

// ---------------- Launch ----------------

extern "C" void kernel_launch(void* const* d_in, const int* in_sizes, int n_in,
                              void* d_out, int out_size)
{
    (void)in_sizes; (void)n_in; (void)out_size;
    const float* x     = (const float*)d_in[0];
    const float* w_q   = (const float*)d_in[1];
    const float* b_q   = (const float*)d_in[2];
    const float* w_K   = (const float*)d_in[3];
    const float* b_K   = (const float*)d_in[4];
    const float* w_V   = (const float*)d_in[5];
    const float* b_V   = (const float*)d_in[6];
    const float* w_Q   = (const float*)d_in[7];
    const float* b_Q   = (const float*)d_in[8];
    const float* w_k   = (const float*)d_in[9];
    const float* b_k   = (const float*)d_in[10];
    const float* w_v   = (const float*)d_in[11];
    const float* b_v   = (const float*)d_in[12];
    const float* gamma = (const float*)d_in[13];
    float* out = (float*)d_out;

    const int proj_smem = PROJ_SMEM_FLOATS * 4;                  // 52480 B
    const int attn_smem = (64*136 + 64*68 + 64*68 + 64*136) * 4; // 104448 B

    cudaFuncSetAttribute(projA_kernel, cudaFuncAttributeMaxDynamicSharedMemorySize, proj_smem);
    cudaFuncSetAttribute(projP_kernel, cudaFuncAttributeMaxDynamicSharedMemorySize, proj_smem);
    cudaFuncSetAttribute(projC_kernel, cudaFuncAttributeMaxDynamicSharedMemorySize, proj_smem);
    cudaFuncSetAttribute(attn_kernel<false>, cudaFuncAttributeMaxDynamicSharedMemorySize, attn_smem);
    cudaFuncSetAttribute(attn_kernel<true>,  cudaFuncAttributeMaxDynamicSharedMemorySize, attn_smem);

    // Projections for stage 1 + stage 2 queries.
    projA_kernel<<<dim3(B_*N_/64, 3), 256, proj_smem>>>(x, w_K, b_K, w_V, b_V, w_Q, b_Q);
    projP_kernel<<<dim3(B_*N4_/64), 256, proj_smem>>>(x, w_q, b_q);

    // Stage 1 attention: split-K over 2 halves (256 CTAs), then combine.
    attn_kernel<false><<<dim3(N4_/64, B_, 2), 256, attn_smem>>>(nullptr, nullptr, nullptr);
    combine_kernel<<<(B_*N4_*16)/256, 256>>>();

    // Stage 2 projections from stage1 output.
    projC_kernel<<<dim3(B_*N4_/64, 2), 256, proj_smem>>>(w_k, b_k, w_v, b_v);

    // Stage 2 attention + residual epilogue (512 CTAs).
    attn_kernel<true><<<dim3(N_/64, B_), 256, attn_smem>>>(out, x, gamma);
}

// round 11
// speedup vs baseline: 2.2306x; 2.2306x over previous
#include <cuda_runtime.h>
#include <cstdint>
#include <cstddef>

#define B_  8
#define C_  64
#define N_  4096
#define N4_ 1024
#define SPLIT1 4
#define BN4 (B_*N4_)

// Scratch (static device globals).
__device__ float g_K [B_*N_*C_];   // (b,n,c)  keys   stage1, n-major
__device__ float g_V [B_*C_*N_];   // (b,c,n)  values stage1, c-major
__device__ float g_Q [B_*N_*C_];   // (b,n,c)  queries stage2, n-major
__device__ float g_qp[B_*N4_*C_];  // (b,j,c)  pooled queries stage1, n-major
__device__ float g_o1[B_*N4_*C_];  // (b,j,c)  stage1 output, n-major
__device__ float g_kp[B_*N4_*C_];  // (b,j,c)  keys   stage2, n-major
__device__ float g_vp[B_*C_*N4_];  // (b,c,j)  values stage2, c-major
// Split-K stage1 partials (4 parts).
__device__ float g_po[SPLIT1*BN4*C_];
__device__ float g_m2[SPLIT1*BN4];
__device__ float g_l2[SPLIT1*BN4];

typedef unsigned long long u64;
typedef unsigned int u32;

__device__ __forceinline__ u64 pack2(float x, float y) {
    u64 r; asm("mov.b64 %0, {%1,%2};" : "=l"(r) : "f"(x), "f"(y)); return r;
}
__device__ __forceinline__ float2 unpk(u64 v) {
    float2 r; asm("mov.b64 {%0,%1}, %2;" : "=f"(r.x), "=f"(r.y) : "l"(v)); return r;
}
__device__ __forceinline__ void fma2(u64& d, u64 a, u64 b) {
    asm("fma.rn.f32x2 %0, %1, %2, %0;" : "+l"(d) : "l"(a), "l"(b));
}
__device__ __forceinline__ u32 to_tf32(float x) {
    u32 r; asm("cvt.rna.tf32.f32 %0, %1;" : "=r"(r) : "f"(x)); return r;
}
__device__ __forceinline__ void mma_tf32(float c[4], u32 a0, u32 a1, u32 a2, u32 a3,
                                         u32 b0, u32 b1) {
    asm volatile(
        "mma.sync.aligned.m16n8k8.row.col.f32.tf32.tf32.f32 "
        "{%0,%1,%2,%3},{%4,%5,%6,%7},{%8,%9},{%0,%1,%2,%3};"
        : "+f"(c[0]), "+f"(c[1]), "+f"(c[2]), "+f"(c[3])
        : "r"(a0), "r"(a1), "r"(a2), "r"(a3), "r"(b0), "r"(b1));
}

union F4U { float4 v; float f[4]; u64 u[2]; };

// ================= Projection GEMM (64x64 W @ 64x64 X tile) ================
#define PW 136
#define PX 68
#define PROJ_SMEM_FLOATS (64*PW + 64*PX + 64)

__device__ __forceinline__ void load_w_dup(const float* __restrict__ w,
                                           const float* __restrict__ bias,
                                           float* sWTd, float* sb, int tid)
{
    for (int i = tid; i < 4096; i += 256) {
        int o = i >> 6, c = i & 63;
        float v = w[i];
        sWTd[c * PW + 2 * o]     = v;
        sWTd[c * PW + 2 * o + 1] = v;
    }
    if (tid < 64) sb[tid] = bias[tid];
}

__device__ __forceinline__ void gemm_tile(const float* sWTd, const float* sX,
                                          const float* sb, u64 acc2[4][2],
                                          int tx, int ty)
{
    #pragma unroll
    for (int i = 0; i < 4; i++) {
        float b = sb[4 * ty + i];
        u64 bb = pack2(b, b);
        acc2[i][0] = bb; acc2[i][1] = bb;
    }
    #pragma unroll 4
    for (int k = 0; k < 64; k++) {
        F4U wa, wb, x;
        wa.v = *(const float4*)(sWTd + k * PW + 8 * ty);
        wb.v = *(const float4*)(sWTd + k * PW + 8 * ty + 4);
        x.v  = *(const float4*)(sX + k * PX + 4 * tx);
        fma2(acc2[0][0], wa.u[0], x.u[0]); fma2(acc2[0][1], wa.u[0], x.u[1]);
        fma2(acc2[1][0], wa.u[1], x.u[0]); fma2(acc2[1][1], wa.u[1], x.u[1]);
        fma2(acc2[2][0], wb.u[0], x.u[0]); fma2(acc2[2][1], wb.u[0], x.u[1]);
        fma2(acc2[3][0], wb.u[1], x.u[0]); fma2(acc2[3][1], wb.u[1], x.u[1]);
    }
}

__device__ __forceinline__ void store_cmajor(float* __restrict__ dst, int nstride,
                                             u64 acc2[4][2], int tx, int ty)
{
    #pragma unroll
    for (int i = 0; i < 4; i++) {
        float2 a0 = unpk(acc2[i][0]), a1 = unpk(acc2[i][1]);
        *(float4*)(dst + (size_t)(4 * ty + i) * nstride + 4 * tx) =
            make_float4(a0.x, a0.y, a1.x, a1.y);
    }
}

__device__ __forceinline__ void store_nmajor(float* __restrict__ dst,
                                             u64 acc2[4][2], int tx, int ty)
{
    float2 r[4][2];
    #pragma unroll
    for (int i = 0; i < 4; i++) {
        r[i][0] = unpk(acc2[i][0]); r[i][1] = unpk(acc2[i][1]);
    }
    #pragma unroll
    for (int jj = 0; jj < 4; jj++) {
        float v0 = (jj & 1) ? r[0][jj >> 1].y : r[0][jj >> 1].x;
        float v1 = (jj & 1) ? r[1][jj >> 1].y : r[1][jj >> 1].x;
        float v2 = (jj & 1) ? r[2][jj >> 1].y : r[2][jj >> 1].x;
        float v3 = (jj & 1) ? r[3][jj >> 1].y : r[3][jj >> 1].x;
        *(float4*)(dst + (size_t)(4 * tx + jj) * 64 + 4 * ty) =
            make_float4(v0, v1, v2, v3);
    }
}

// K (n-major), V (c-major), Q (n-major) projections from x.
__global__ __launch_bounds__(256, 2)
void projA_kernel(const float* __restrict__ x,
                  const float* __restrict__ wK, const float* __restrict__ bK,
                  const float* __restrict__ wV, const float* __restrict__ bV,
                  const float* __restrict__ wQ, const float* __restrict__ bQ)
{
    extern __shared__ float sh[];
    float* sWTd = sh;
    float* sX   = sh + 64 * PW;
    float* sb   = sX + 64 * PX;
    int which = blockIdx.y;
    int tid = threadIdx.x;
    const float* w  = which == 0 ? wK : (which == 1 ? wV : wQ);
    const float* bs = which == 0 ? bK : (which == 1 ? bV : bQ);
    load_w_dup(w, bs, sWTd, sb, tid);

    int gpos0 = blockIdx.x * 64;
    int b = gpos0 >> 12, n0 = gpos0 & (N_ - 1);
    const float* xb = x + (size_t)b * C_ * N_;
    for (int i = tid; i < 1024; i += 256) {
        int c = i >> 4, pg = (i & 15) * 4;
        *(float4*)(sX + c * PX + pg) = *(const float4*)(xb + (size_t)c * N_ + n0 + pg);
    }
    __syncthreads();

    int tx = tid & 15, ty = tid >> 4;
    u64 acc2[4][2];
    gemm_tile(sWTd, sX, sb, acc2, tx, ty);

    if (which == 0)      store_nmajor(g_K + (size_t)gpos0 * 64, acc2, tx, ty);
    else if (which == 2) store_nmajor(g_Q + (size_t)gpos0 * 64, acc2, tx, ty);
    else                 store_cmajor(g_V + (size_t)b * C_ * N_ + n0, N_, acc2, tx, ty);
}

// Pooled q (n-major).
__global__ __launch_bounds__(256, 2)
void projP_kernel(const float* __restrict__ x,
                  const float* __restrict__ wq, const float* __restrict__ bq)
{
    extern __shared__ float sh[];
    float* sWTd = sh;
    float* sX   = sh + 64 * PW;
    float* sb   = sX + 64 * PX;
    int tid = threadIdx.x;
    load_w_dup(wq, bq, sWTd, sb, tid);

    int gpos0 = blockIdx.x * 64;
    int b = gpos0 >> 10, j0 = gpos0 & (N4_ - 1);
    const float* xb = x + (size_t)b * C_ * N_;
    for (int i = tid; i < 4096; i += 256) {
        int c = i >> 6, j = i & 63;
        int jj = j0 + j;
        int r = jj >> 5, col = jj & 31;
        const float* p = xb + (size_t)c * N_ + r * 128 + col * 2;
        float2 a = *(const float2*)p;
        float2 d = *(const float2*)(p + 64);
        sX[c * PX + j] = 0.25f * (a.x + a.y + d.x + d.y);
    }
    __syncthreads();

    int tx = tid & 15, ty = tid >> 4;
    u64 acc2[4][2];
    gemm_tile(sWTd, sX, sb, acc2, tx, ty);
    store_nmajor(g_qp + (size_t)gpos0 * 64, acc2, tx, ty);
}

// kp (n-major), vp (c-major) from stage1 output.
__global__ __launch_bounds__(256, 2)
void projC_kernel(const float* __restrict__ wk, const float* __restrict__ bk,
                  const float* __restrict__ wv, const float* __restrict__ bv)
{
    extern __shared__ float sh[];
    float* sWTd = sh;
    float* sX   = sh + 64 * PW;
    float* sb   = sX + 64 * PX;
    int which = blockIdx.y;
    int tid = threadIdx.x;
    load_w_dup(which ? wv : wk, which ? bv : bk, sWTd, sb, tid);

    int gpos0 = blockIdx.x * 64;
    int b = gpos0 >> 10, j0 = gpos0 & (N4_ - 1);
    const float* src = g_o1 + (size_t)gpos0 * 64;
    for (int i = tid; i < 1024; i += 256) {
        int pos = i >> 4, cg = (i & 15) * 4;
        float4 v = *(const float4*)(src + (size_t)pos * 64 + cg);
        sX[(cg + 0) * PX + pos] = v.x;
        sX[(cg + 1) * PX + pos] = v.y;
        sX[(cg + 2) * PX + pos] = v.z;
        sX[(cg + 3) * PX + pos] = v.w;
    }
    __syncthreads();

    int tx = tid & 15, ty = tid >> 4;
    u64 acc2[4][2];
    gemm_tile(sWTd, sX, sb, acc2, tx, ty);
    if (which == 0) store_nmajor(g_kp + (size_t)gpos0 * 64, acc2, tx, ty);
    else            store_cmajor(g_vp + (size_t)b * C_ * N4_ + j0, N4_, acc2, tx, ty);
}

// ================= tf32 tensor-core flash attention ========================
// CTA = 128 q-rows, 8 warps x 16 q-rows each, full 64-key tiles.
// smem perm layout along the contraction dim: pos(d) = (d&3)*16 + (d>>2),
// so mma fragments load as contiguous LDS.64 / LDS.128.
// sQ[q][perm d], sK[key][perm d], sV[c][perm key], sP[q][perm key]. Pitch 68.
#define PT 68

template<bool FINAL>
__global__ __launch_bounds__(256, 2)
void attn_kernel(float* __restrict__ outg,
                 const float* __restrict__ xr,
                 const float* __restrict__ gp)
{
    constexpr int NKEY = FINAL ? 1024 : 4096;
    constexpr int NQ   = FINAL ? 4096 : 1024;

    extern __shared__ float sh[];
    float* sQ = sh;              // 128*68
    float* sK = sQ + 128 * PT;   // 64*68
    float* sV = sK + 64 * PT;    // 64*68
    float* sP = sV + 64 * PT;    // 128*68

    int tid = threadIdx.x;
    int wid = tid >> 5, lane = tid & 31;
    int grp = lane >> 2, qd = lane & 3;
    int b = blockIdx.y, qt = blockIdx.x;
    int part = FINAL ? 0 : blockIdx.z;

    const float* Qb = (FINAL ? g_Q  : g_qp) + ((size_t)b * NQ + qt * 128) * 64;
    const float* Kb = (FINAL ? g_kp : g_K ) + (size_t)b * NKEY * 64;
    const float* Vb = (FINAL ? g_vp : g_V ) + (size_t)b * C_ * NKEY;

    // Q tile (128 rows), perm + tf32.
    for (int i = tid; i < 2048; i += 256) {
        int q = i >> 4, t = i & 15;
        float4 v = *(const float4*)(Qb + (size_t)q * 64 + 4 * t);
        u32* dst = (u32*)(sQ + q * PT);
        dst[t]      = to_tf32(v.x);
        dst[16 + t] = to_tf32(v.y);
        dst[32 + t] = to_tf32(v.z);
        dst[48 + t] = to_tf32(v.w);
    }

    float m0 = -1e30f, m1 = -1e30f, l0 = 0.f, l1 = 0.f;
    float oc[8][4];
    #pragma unroll
    for (int nt = 0; nt < 8; nt++)
        #pragma unroll
        for (int k = 0; k < 4; k++) oc[nt][k] = 0.f;
    __syncthreads();

    // Persistent A fragments (Q rows r0 = wid*16+grp, r1 = r0+8), all 8 k-steps.
    int r0 = wid * 16 + grp;
    u32 aQ0[16], aQ1[16];
    {
        const u32* p0 = (const u32*)(sQ + r0 * PT) + qd * 16;
        const u32* p1 = (const u32*)(sQ + (r0 + 8) * PT) + qd * 16;
        #pragma unroll
        for (int t = 0; t < 4; t++) {
            uint4 x0 = *(const uint4*)(p0 + 4 * t);
            uint4 x1 = *(const uint4*)(p1 + 4 * t);
            aQ0[4*t] = x0.x; aQ0[4*t+1] = x0.y; aQ0[4*t+2] = x0.z; aQ0[4*t+3] = x0.w;
            aQ1[4*t] = x1.x; aQ1[4*t+1] = x1.y; aQ1[4*t+2] = x1.z; aQ1[4*t+3] = x1.w;
        }
    }

    int kt0 = FINAL ? 0 : part * (NKEY / 64 / SPLIT1);
    int nkt = FINAL ? NKEY / 64 : NKEY / 64 / SPLIT1;
    for (int kk = 0; kk < nkt; kk++) {
        int kt = kt0 + kk;
        __syncthreads();
        // K tile (64 keys), perm + tf32.
        for (int i = tid; i < 1024; i += 256) {
            int key = i >> 4, t = i & 15;
            float4 v = *(const float4*)(Kb + ((size_t)kt * 64 + key) * 64 + 4 * t);
            u32* dst = (u32*)(sK + key * PT);
            dst[t]      = to_tf32(v.x);
            dst[16 + t] = to_tf32(v.y);
            dst[32 + t] = to_tf32(v.z);
            dst[48 + t] = to_tf32(v.w);
        }
        // V tile (c-major), perm over key + tf32.
        for (int i = tid; i < 1024; i += 256) {
            int c = i >> 4, t = i & 15;
            float4 v = *(const float4*)(Vb + (size_t)c * NKEY + kt * 64 + 4 * t);
            u32* dst = (u32*)(sV + c * PT);
            dst[t]      = to_tf32(v.x);
            dst[16 + t] = to_tf32(v.y);
            dst[32 + t] = to_tf32(v.z);
            dst[48 + t] = to_tf32(v.w);
        }
        __syncthreads();

        // S = Q K^T : 8 n-tiles x 8 k-steps of m16n8k8.
        float sc[8][4];
        #pragma unroll
        for (int nt = 0; nt < 8; nt++) {
            sc[nt][0] = 0.f; sc[nt][1] = 0.f; sc[nt][2] = 0.f; sc[nt][3] = 0.f;
            const u32* pB = (const u32*)(sK + (8 * nt + grp) * PT) + qd * 16;
            #pragma unroll
            for (int s = 0; s < 8; s++) {
                uint2 bb = *(const uint2*)(pB + 2 * s);
                mma_tf32(sc[nt], aQ0[2*s], aQ1[2*s], aQ0[2*s+1], aQ1[2*s+1],
                         bb.x, bb.y);
            }
        }

        // Online softmax (rows r0, r0+8 are warp-private).
        float rx0 = -1e30f, rx1 = -1e30f;
        #pragma unroll
        for (int nt = 0; nt < 8; nt++) {
            rx0 = fmaxf(rx0, fmaxf(sc[nt][0], sc[nt][1]));
            rx1 = fmaxf(rx1, fmaxf(sc[nt][2], sc[nt][3]));
        }
        rx0 = fmaxf(rx0, __shfl_xor_sync(0xffffffffu, rx0, 1));
        rx0 = fmaxf(rx0, __shfl_xor_sync(0xffffffffu, rx0, 2));
        rx1 = fmaxf(rx1, __shfl_xor_sync(0xffffffffu, rx1, 1));
        rx1 = fmaxf(rx1, __shfl_xor_sync(0xffffffffu, rx1, 2));
        float mn0 = fmaxf(m0, rx0), mn1 = fmaxf(m1, rx1);
        float al0 = __expf(m0 - mn0), al1 = __expf(m1 - mn1);
        m0 = mn0; m1 = mn1;

        u32* pr0 = (u32*)(sP + r0 * PT);
        u32* pr1 = (u32*)(sP + (r0 + 8) * PT);
        int pe = ((2 * qd) & 3) * 16 + (qd >> 1);
        float sum0 = 0.f, sum1 = 0.f;
        #pragma unroll
        for (int nt = 0; nt < 8; nt++) {
            float p00 = __expf(sc[nt][0] - mn0);
            float p01 = __expf(sc[nt][1] - mn0);
            float p10 = __expf(sc[nt][2] - mn1);
            float p11 = __expf(sc[nt][3] - mn1);
            sum0 += p00 + p01; sum1 += p10 + p11;
            pr0[pe + 2*nt]      = to_tf32(p00);
            pr0[pe + 2*nt + 16] = to_tf32(p01);
            pr1[pe + 2*nt]      = to_tf32(p10);
            pr1[pe + 2*nt + 16] = to_tf32(p11);
        }
        sum0 += __shfl_xor_sync(0xffffffffu, sum0, 1);
        sum0 += __shfl_xor_sync(0xffffffffu, sum0, 2);
        sum1 += __shfl_xor_sync(0xffffffffu, sum1, 1);
        sum1 += __shfl_xor_sync(0xffffffffu, sum1, 2);
        l0 = l0 * al0 + sum0;
        l1 = l1 * al1 + sum1;
        #pragma unroll
        for (int nt = 0; nt < 8; nt++) {
            oc[nt][0] *= al0; oc[nt][1] *= al0;
            oc[nt][2] *= al1; oc[nt][3] *= al1;
        }
        __syncwarp();

        // PV: A = own P rows (perm over key), B = V tiles.
        u32 pP0[16], pP1[16];
        {
            const u32* p0 = (const u32*)(sP + r0 * PT) + qd * 16;
            const u32* p1 = (const u32*)(sP + (r0 + 8) * PT) + qd * 16;
            #pragma unroll
            for (int t = 0; t < 4; t++) {
                uint4 x0 = *(const uint4*)(p0 + 4 * t);
                uint4 x1 = *(const uint4*)(p1 + 4 * t);
                pP0[4*t] = x0.x; pP0[4*t+1] = x0.y; pP0[4*t+2] = x0.z; pP0[4*t+3] = x0.w;
                pP1[4*t] = x1.x; pP1[4*t+1] = x1.y; pP1[4*t+2] = x1.z; pP1[4*t+3] = x1.w;
            }
        }
        #pragma unroll
        for (int nt = 0; nt < 8; nt++) {
            const u32* pB = (const u32*)(sV + (8 * nt + grp) * PT) + qd * 16;
            #pragma unroll
            for (int s = 0; s < 8; s++) {
                uint2 bb = *(const uint2*)(pB + 2 * s);
                mma_tf32(oc[nt], pP0[2*s], pP1[2*s], pP0[2*s+1], pP1[2*s+1],
                         bb.x, bb.y);
            }
        }
    }

    if (!FINAL) {
        // Split-K partial: unnormalized acc + (m,l).
        size_t mlidx = (size_t)(part * B_ + b) * N4_ + qt * 128 + r0;
        #pragma unroll
        for (int nt = 0; nt < 8; nt++) {
            *(float2*)(g_po + mlidx * 64 + 8 * nt + 2 * qd) =
                make_float2(oc[nt][0], oc[nt][1]);
            *(float2*)(g_po + (mlidx + 8) * 64 + 8 * nt + 2 * qd) =
                make_float2(oc[nt][2], oc[nt][3]);
        }
        if (qd == 0) {
            g_m2[mlidx] = m0; g_l2[mlidx] = l0;
            g_m2[mlidx + 8] = m1; g_l2[mlidx + 8] = l1;
        }
    } else {
        // Normalize into sP (plain [q][c]), then fused residual write.
        float inv0 = 1.f / l0, inv1 = 1.f / l1;
        __syncthreads();
        #pragma unroll
        for (int nt = 0; nt < 8; nt++) {
            *(float2*)(sP + r0 * PT + 8 * nt + 2 * qd) =
                make_float2(oc[nt][0] * inv0, oc[nt][1] * inv0);
            *(float2*)(sP + (r0 + 8) * PT + 8 * nt + 2 * qd) =
                make_float2(oc[nt][2] * inv1, oc[nt][3] * inv1);
        }
        __syncthreads();
        float gamma = gp[0];
        int n0 = qt * 128;
        #pragma unroll 4
        for (int r2 = 0; r2 < 32; r2++) {
            int idx = r2 * 256 + tid;
            int c = idx >> 7, nl = idx & 127;
            size_t ga = ((size_t)b * 64 + c) * (size_t)N_ + n0 + nl;
            outg[ga] = gamma * sP[nl * PT + c] + xr[ga];
        }
    }
}

// Merge the 4 split-K partials: exact flash combine.
__global__ __launch_bounds__(256)
void combine_kernel()
{
    int idx = blockIdx.x * 256 + threadIdx.x;   // over BN4*16 float4 groups
    int row = idx >> 4, c4 = (idx & 15) * 4;
    float mv[SPLIT1], lv[SPLIT1];
    float M = -1e30f;
    #pragma unroll
    for (int p = 0; p < SPLIT1; p++) {
        mv[p] = g_m2[p * BN4 + row];
        lv[p] = g_l2[p * BN4 + row];
        M = fmaxf(M, mv[p]);
    }
    float w[SPLIT1], ltot = 0.f;
    #pragma unroll
    for (int p = 0; p < SPLIT1; p++) {
        w[p] = __expf(mv[p] - M);
        ltot += lv[p] * w[p];
    }
    float inv = 1.f / ltot;
    float4 acc = make_float4(0.f, 0.f, 0.f, 0.f);
    #pragma unroll
    for (int p = 0; p < SPLIT1; p++) {
        float4 a = *(const float4*)(g_po + ((size_t)p * BN4 + row) * 64 + c4);
        acc.x += a.x * w[p]; acc.y += a.y * w[p];
        acc.z += a.z * w[p]; acc.w += a.w * w[p];
    }
    *(float4*)(g_o1 + (size_t)row * 64 + c4) =
        make_float4(acc.x * inv, acc.y * inv, acc.z * inv, acc.w * inv);
}

// ---------------- Launch ----------------

extern "C" void kernel_launch(void* const* d_in, const int* in_sizes, int n_in,
                              void* d_out, int out_size)
{
    (void)in_sizes; (void)n_in; (void)out_size;
    const float* x     = (const float*)d_in[0];
    const float* w_q   = (const float*)d_in[1];
    const float* b_q   = (const float*)d_in[2];
    const float* w_K   = (const float*)d_in[3];
    const float* b_K   = (const float*)d_in[4];
    const float* w_V   = (const float*)d_in[5];
    const float* b_V   = (const float*)d_in[6];
    const float* w_Q   = (const float*)d_in[7];
    const float* b_Q   = (const float*)d_in[8];
    const float* w_k   = (const float*)d_in[9];
    const float* b_k   = (const float*)d_in[10];
    const float* w_v   = (const float*)d_in[11];
    const float* b_v   = (const float*)d_in[12];
    const float* gamma = (const float*)d_in[13];
    float* out = (float*)d_out;

    const int proj_smem = PROJ_SMEM_FLOATS * 4;   // 52480 B
    const int attn_smem = 384 * PT * 4;           // 104448 B

    cudaFuncSetAttribute(projA_kernel, cudaFuncAttributeMaxDynamicSharedMemorySize, proj_smem);
    cudaFuncSetAttribute(projP_kernel, cudaFuncAttributeMaxDynamicSharedMemorySize, proj_smem);
    cudaFuncSetAttribute(projC_kernel, cudaFuncAttributeMaxDynamicSharedMemorySize, proj_smem);
    cudaFuncSetAttribute(attn_kernel<false>, cudaFuncAttributeMaxDynamicSharedMemorySize, attn_smem);
    cudaFuncSetAttribute(attn_kernel<true>,  cudaFuncAttributeMaxDynamicSharedMemorySize, attn_smem);

    // Projections for stage 1 + stage 2 queries.
    projA_kernel<<<dim3(B_*N_/64, 3), 256, proj_smem>>>(x, w_K, b_K, w_V, b_V, w_Q, b_Q);
    projP_kernel<<<dim3(B_*N4_/64), 256, proj_smem>>>(x, w_q, b_q);

    // Stage 1 attention: split-K over 4 parts (8 x 8 x 4 = 256 CTAs), combine.
    attn_kernel<false><<<dim3(N4_/128, B_, SPLIT1), 256, attn_smem>>>(nullptr, nullptr, nullptr);
    combine_kernel<<<(BN4*16)/256, 256>>>();

    // Stage 2 projections from stage1 output.
    projC_kernel<<<dim3(B_*N4_/64, 2), 256, proj_smem>>>(w_k, b_k, w_v, b_v);

    // Stage 2 attention + residual epilogue (32 x 8 = 256 CTAs).
    attn_kernel<true><<<dim3(N_/128, B_), 256, attn_smem>>>(out, x, gamma);
}

// round 12
// speedup vs baseline: 4.7023x; 2.1081x over previous
#include <cuda_runtime.h>
#include <cstdint>
#include <cstddef>

#define B_  8
#define C_  64
#define N_  4096
#define N4_ 1024
#define SPLIT1 4
#define BN4 (B_*N4_)

typedef unsigned long long u64;
typedef unsigned int u32;

// Scratch. bf16 operands stored as bf16x2 words in the attention frag layout:
// per row, 32 words over the 64-elt contraction dim, word w at perm
// p(w) = (w&3)*8 + (w>>2).
__device__ u32 g_K [B_*N_*32];          // (b,key)[32]   stage1 keys, perm-of-d
__device__ u32 g_V [B_*C_*(N_/64)*32];  // (b,c,ktile)[32] stage1 values, perm-of-key
__device__ u32 g_Q [B_*N_*32];          // (b,q)[32]     stage2 queries
__device__ u32 g_qp[B_*N4_*32];         // (b,j)[32]     stage1 pooled queries
__device__ u32 g_kp[B_*N4_*32];         // (b,j)[32]     stage2 keys
__device__ u32 g_vp[B_*C_*(N4_/64)*32]; // (b,c,ktile)[32] stage2 values
__device__ float g_o1[B_*N4_*C_];       // stage1 output fp32 n-major
__device__ float g_po[SPLIT1*BN4*C_];   // split-K partials
__device__ float g_m2[SPLIT1*BN4];
__device__ float g_l2[SPLIT1*BN4];

__device__ __forceinline__ u64 pack2(float x, float y) {
    u64 r; asm("mov.b64 %0, {%1,%2};" : "=l"(r) : "f"(x), "f"(y)); return r;
}
__device__ __forceinline__ float2 unpk(u64 v) {
    float2 r; asm("mov.b64 {%0,%1}, %2;" : "=f"(r.x), "=f"(r.y) : "l"(v)); return r;
}
__device__ __forceinline__ void fma2(u64& d, u64 a, u64 b) {
    asm("fma.rn.f32x2 %0, %1, %2, %0;" : "+l"(d) : "l"(a), "l"(b));
}
__device__ __forceinline__ u32 bf2(float lo, float hi) {
    u32 r; asm("cvt.rn.bf16x2.f32 %0, %1, %2;" : "=r"(r) : "f"(hi), "f"(lo)); return r;
}
__device__ __forceinline__ int permw(int w) { return (w & 3) * 8 + (w >> 2); }

__device__ __forceinline__ void mma_bf16(float c[4], u32 a0, u32 a1, u32 a2, u32 a3,
                                         u32 b0, u32 b1) {
    asm volatile(
        "mma.sync.aligned.m16n8k16.row.col.f32.bf16.bf16.f32 "
        "{%0,%1,%2,%3},{%4,%5,%6,%7},{%8,%9},{%0,%1,%2,%3};"
        : "+f"(c[0]), "+f"(c[1]), "+f"(c[2]), "+f"(c[3])
        : "r"(a0), "r"(a1), "r"(a2), "r"(a3), "r"(b0), "r"(b1));
}

union F4U { float4 v; float f[4]; u64 u[2]; };

// ================= Projection GEMM (64x64 W @ 64x64 X tile) ================
#define PW 136
#define PX 68
#define PROJ_SMEM_FLOATS (64*PW + 64*PX + 64)

__device__ __forceinline__ void load_w_dup(const float* __restrict__ w,
                                           const float* __restrict__ bias,
                                           float* sWTd, float* sb, int tid)
{
    for (int i = tid; i < 4096; i += 256) {
        int o = i >> 6, c = i & 63;
        float v = w[i];
        sWTd[c * PW + 2 * o]     = v;
        sWTd[c * PW + 2 * o + 1] = v;
    }
    if (tid < 64) sb[tid] = bias[tid];
}

__device__ __forceinline__ void gemm_tile(const float* sWTd, const float* sX,
                                          const float* sb, u64 acc2[4][2],
                                          int tx, int ty)
{
    #pragma unroll
    for (int i = 0; i < 4; i++) {
        float b = sb[4 * ty + i];
        u64 bb = pack2(b, b);
        acc2[i][0] = bb; acc2[i][1] = bb;
    }
    #pragma unroll 4
    for (int k = 0; k < 64; k++) {
        F4U wa, wb, x;
        wa.v = *(const float4*)(sWTd + k * PW + 8 * ty);
        wb.v = *(const float4*)(sWTd + k * PW + 8 * ty + 4);
        x.v  = *(const float4*)(sX + k * PX + 4 * tx);
        fma2(acc2[0][0], wa.u[0], x.u[0]); fma2(acc2[0][1], wa.u[0], x.u[1]);
        fma2(acc2[1][0], wa.u[1], x.u[0]); fma2(acc2[1][1], wa.u[1], x.u[1]);
        fma2(acc2[2][0], wb.u[0], x.u[0]); fma2(acc2[2][1], wb.u[0], x.u[1]);
        fma2(acc2[3][0], wb.u[1], x.u[0]); fma2(acc2[3][1], wb.u[1], x.u[1]);
    }
}

// n-major bf16 perm store: dst = &g[row0*32]; rows = positions, words over channels.
__device__ __forceinline__ void store_nmajor_bf16(u32* __restrict__ dst,
                                                  u64 acc2[4][2], int tx, int ty)
{
    int p0 = permw(2 * ty), p1 = permw(2 * ty + 1);
    float2 a[4][2];
    #pragma unroll
    for (int i = 0; i < 4; i++) { a[i][0] = unpk(acc2[i][0]); a[i][1] = unpk(acc2[i][1]); }
    u32* r;
    r = dst + (size_t)(4*tx + 0) * 32;
    r[p0] = bf2(a[0][0].x, a[1][0].x); r[p1] = bf2(a[2][0].x, a[3][0].x);
    r = dst + (size_t)(4*tx + 1) * 32;
    r[p0] = bf2(a[0][0].y, a[1][0].y); r[p1] = bf2(a[2][0].y, a[3][0].y);
    r = dst + (size_t)(4*tx + 2) * 32;
    r[p0] = bf2(a[0][1].x, a[1][1].x); r[p1] = bf2(a[2][1].x, a[3][1].x);
    r = dst + (size_t)(4*tx + 3) * 32;
    r[p0] = bf2(a[0][1].y, a[1][1].y); r[p1] = bf2(a[2][1].y, a[3][1].y);
}

// c-major bf16 perm store (V): dst = &g[((b*64)*NT + kt)*32], cstride = NT*32.
__device__ __forceinline__ void store_cmajor_bf16(u32* __restrict__ dst, int cstride,
                                                  u64 acc2[4][2], int tx, int ty)
{
    int p0 = permw(2 * tx), p1 = permw(2 * tx + 1);
    #pragma unroll
    for (int i = 0; i < 4; i++) {
        float2 a0 = unpk(acc2[i][0]), a1 = unpk(acc2[i][1]);
        u32* row = dst + (size_t)(4 * ty + i) * cstride;
        row[p0] = bf2(a0.x, a0.y);
        row[p1] = bf2(a1.x, a1.y);
    }
}

__global__ __launch_bounds__(256, 2)
void projA_kernel(const float* __restrict__ x,
                  const float* __restrict__ wK, const float* __restrict__ bK,
                  const float* __restrict__ wV, const float* __restrict__ bV,
                  const float* __restrict__ wQ, const float* __restrict__ bQ)
{
    extern __shared__ float sh[];
    float* sWTd = sh;
    float* sX   = sh + 64 * PW;
    float* sb   = sX + 64 * PX;
    int which = blockIdx.y;
    int tid = threadIdx.x;
    const float* w  = which == 0 ? wK : (which == 1 ? wV : wQ);
    const float* bs = which == 0 ? bK : (which == 1 ? bV : bQ);
    load_w_dup(w, bs, sWTd, sb, tid);

    int gpos0 = blockIdx.x * 64;
    int b = gpos0 >> 12, n0 = gpos0 & (N_ - 1);
    const float* xb = x + (size_t)b * C_ * N_;
    for (int i = tid; i < 1024; i += 256) {
        int c = i >> 4, pg = (i & 15) * 4;
        *(float4*)(sX + c * PX + pg) = *(const float4*)(xb + (size_t)c * N_ + n0 + pg);
    }
    __syncthreads();

    int tx = tid & 15, ty = tid >> 4;
    u64 acc2[4][2];
    gemm_tile(sWTd, sX, sb, acc2, tx, ty);

    if (which == 0)      store_nmajor_bf16(g_K + (size_t)gpos0 * 32, acc2, tx, ty);
    else if (which == 2) store_nmajor_bf16(g_Q + (size_t)gpos0 * 32, acc2, tx, ty);
    else store_cmajor_bf16(g_V + ((size_t)b * 64 * 64 + (n0 >> 6)) * 32, 64*32,
                           acc2, tx, ty);
}

__global__ __launch_bounds__(256, 2)
void projP_kernel(const float* __restrict__ x,
                  const float* __restrict__ wq, const float* __restrict__ bq)
{
    extern __shared__ float sh[];
    float* sWTd = sh;
    float* sX   = sh + 64 * PW;
    float* sb   = sX + 64 * PX;
    int tid = threadIdx.x;
    load_w_dup(wq, bq, sWTd, sb, tid);

    int gpos0 = blockIdx.x * 64;
    int b = gpos0 >> 10, j0 = gpos0 & (N4_ - 1);
    const float* xb = x + (size_t)b * C_ * N_;
    for (int i = tid; i < 4096; i += 256) {
        int c = i >> 6, j = i & 63;
        int jj = j0 + j;
        int r = jj >> 5, col = jj & 31;
        const float* p = xb + (size_t)c * N_ + r * 128 + col * 2;
        float2 a = *(const float2*)p;
        float2 d = *(const float2*)(p + 64);
        sX[c * PX + j] = 0.25f * (a.x + a.y + d.x + d.y);
    }
    __syncthreads();

    int tx = tid & 15, ty = tid >> 4;
    u64 acc2[4][2];
    gemm_tile(sWTd, sX, sb, acc2, tx, ty);
    store_nmajor_bf16(g_qp + (size_t)gpos0 * 32, acc2, tx, ty);
}

__global__ __launch_bounds__(256, 2)
void projC_kernel(const float* __restrict__ wk, const float* __restrict__ bk,
                  const float* __restrict__ wv, const float* __restrict__ bv)
{
    extern __shared__ float sh[];
    float* sWTd = sh;
    float* sX   = sh + 64 * PW;
    float* sb   = sX + 64 * PX;
    int which = blockIdx.y;
    int tid = threadIdx.x;
    load_w_dup(which ? wv : wk, which ? bv : bk, sWTd, sb, tid);

    int gpos0 = blockIdx.x * 64;
    int b = gpos0 >> 10, j0 = gpos0 & (N4_ - 1);
    const float* src = g_o1 + (size_t)gpos0 * 64;
    for (int i = tid; i < 1024; i += 256) {
        int pos = i >> 4, cg = (i & 15) * 4;
        float4 v = *(const float4*)(src + (size_t)pos * 64 + cg);
        sX[(cg + 0) * PX + pos] = v.x;
        sX[(cg + 1) * PX + pos] = v.y;
        sX[(cg + 2) * PX + pos] = v.z;
        sX[(cg + 3) * PX + pos] = v.w;
    }
    __syncthreads();

    int tx = tid & 15, ty = tid >> 4;
    u64 acc2[4][2];
    gemm_tile(sWTd, sX, sb, acc2, tx, ty);
    if (which == 0) store_nmajor_bf16(g_kp + (size_t)gpos0 * 32, acc2, tx, ty);
    else store_cmajor_bf16(g_vp + ((size_t)b * 64 * 16 + (j0 >> 6)) * 32, 16*32,
                           acc2, tx, ty);
}

// ================= bf16 m16n8k16 flash attention ===========================
// CTA = 128 q-rows, 8 warps x 16 q-rows, 64-key tiles, double-buffered K/V.
// All smem rows: 32 bf16x2 words, pitch 36 (all frag/tile accesses are
// 4-phase-optimal uint4).
#define PR 36

template<bool FINAL>
__global__ __launch_bounds__(256, 2)
void attn_kernel(float* __restrict__ outg,
                 const float* __restrict__ xr,
                 const float* __restrict__ gp)
{
    constexpr int NKEY = FINAL ? 1024 : 4096;
    constexpr int NQ   = FINAL ? 4096 : 1024;
    constexpr int NT   = NKEY / 64;

    extern __shared__ u32 sm[];
    u32* sQ  = sm;                 // 128*36
    u32* sK0 = sQ  + 128 * PR;     // 64*36
    u32* sV0 = sK0 + 64 * PR;
    u32* sK1 = sV0 + 64 * PR;
    u32* sV1 = sK1 + 64 * PR;
    u32* sP  = sV1 + 64 * PR;      // 128*36

    int tid = threadIdx.x;
    int wid = tid >> 5, lane = tid & 31;
    int grp = lane >> 2, qd = lane & 3;
    int b = blockIdx.y, qt = blockIdx.x;
    int part = FINAL ? 0 : blockIdx.z;

    const u32* Qg = (FINAL ? g_Q  : g_qp) + ((size_t)b * NQ + qt * 128) * 32;
    const u32* Kg = (FINAL ? g_kp : g_K ) + (size_t)b * NKEY * 32;
    const u32* Vg = (FINAL ? g_vp : g_V ) + (size_t)b * C_ * NT * 32;

    int nkt = FINAL ? NT : NT / SPLIT1;
    int kt0 = part * nkt;

    // Q tile copy (bf16 perm layout already) : 4 uint4/thread.
    #pragma unroll
    for (int r = 0; r < 4; r++) {
        int idx = r * 256 + tid;
        int row = idx >> 3, q4 = (idx & 7) * 4;
        *(uint4*)(sQ + row * PR + q4) = *(const uint4*)(Qg + (size_t)row * 32 + q4);
    }
    // Tile 0 K,V copy: 2 uint4/thread each.
    #pragma unroll
    for (int r = 0; r < 2; r++) {
        int idx = r * 256 + tid;
        int row = idx >> 3, q4 = (idx & 7) * 4;
        *(uint4*)(sK0 + row * PR + q4) =
            *(const uint4*)(Kg + ((size_t)kt0 * 64 + row) * 32 + q4);
        *(uint4*)(sV0 + row * PR + q4) =
            *(const uint4*)(Vg + ((size_t)row * NT + kt0) * 32 + q4);
    }
    __syncthreads();

    // Persistent Q A-fragments (rows r0, r0+8; 4 k16-steps).
    int r0 = wid * 16 + grp;
    u32 aQ0[8], aQ1[8];
    #pragma unroll
    for (int u = 0; u < 2; u++) {
        uint4 x0 = *(const uint4*)(sQ + r0 * PR + 8 * qd + 4 * u);
        uint4 x1 = *(const uint4*)(sQ + (r0 + 8) * PR + 8 * qd + 4 * u);
        aQ0[4*u] = x0.x; aQ0[4*u+1] = x0.y; aQ0[4*u+2] = x0.z; aQ0[4*u+3] = x0.w;
        aQ1[4*u] = x1.x; aQ1[4*u+1] = x1.y; aQ1[4*u+2] = x1.z; aQ1[4*u+3] = x1.w;
    }

    float m0 = -1e30f, m1 = -1e30f, l0 = 0.f, l1 = 0.f;
    float oc[8][4];
    #pragma unroll
    for (int nt = 0; nt < 8; nt++) {
        oc[nt][0] = 0.f; oc[nt][1] = 0.f; oc[nt][2] = 0.f; oc[nt][3] = 0.f;
    }

    for (int kk = 0; kk < nkt; kk++) {
        const u32* sKc = (kk & 1) ? sK1 : sK0;
        const u32* sVc = (kk & 1) ? sV1 : sV0;
        u32* sKn = (kk & 1) ? sK0 : sK1;
        u32* sVn = (kk & 1) ? sV0 : sV1;

        // Prefetch next tile into registers (latency overlapped with compute).
        uint4 pfK[2], pfV[2];
        bool hasNext = (kk + 1 < nkt);
        if (hasNext) {
            int kt = kt0 + kk + 1;
            #pragma unroll
            for (int r = 0; r < 2; r++) {
                int idx = r * 256 + tid;
                int row = idx >> 3, q4 = (idx & 7) * 4;
                pfK[r] = *(const uint4*)(Kg + ((size_t)kt * 64 + row) * 32 + q4);
                pfV[r] = *(const uint4*)(Vg + ((size_t)row * NT + kt) * 32 + q4);
            }
        }

        // S = Q K^T : per n-tile 2 LDS.128 + 4 mma.
        float sc[8][4];
        #pragma unroll
        for (int nt = 0; nt < 8; nt++) {
            sc[nt][0] = 0.f; sc[nt][1] = 0.f; sc[nt][2] = 0.f; sc[nt][3] = 0.f;
            const u32* bp = sKc + (8 * nt + grp) * PR + 8 * qd;
            uint4 B0 = *(const uint4*)bp;
            uint4 B1 = *(const uint4*)(bp + 4);
            mma_bf16(sc[nt], aQ0[0], aQ1[0], aQ0[1], aQ1[1], B0.x, B0.y);
            mma_bf16(sc[nt], aQ0[2], aQ1[2], aQ0[3], aQ1[3], B0.z, B0.w);
            mma_bf16(sc[nt], aQ0[4], aQ1[4], aQ0[5], aQ1[5], B1.x, B1.y);
            mma_bf16(sc[nt], aQ0[6], aQ1[6], aQ0[7], aQ1[7], B1.z, B1.w);
        }

        // Online softmax (rows r0, r0+8 warp-private; reduce over qd lanes).
        float rx0 = -1e30f, rx1 = -1e30f;
        #pragma unroll
        for (int nt = 0; nt < 8; nt++) {
            rx0 = fmaxf(rx0, fmaxf(sc[nt][0], sc[nt][1]));
            rx1 = fmaxf(rx1, fmaxf(sc[nt][2], sc[nt][3]));
        }
        rx0 = fmaxf(rx0, __shfl_xor_sync(0xffffffffu, rx0, 1));
        rx0 = fmaxf(rx0, __shfl_xor_sync(0xffffffffu, rx0, 2));
        rx1 = fmaxf(rx1, __shfl_xor_sync(0xffffffffu, rx1, 1));
        rx1 = fmaxf(rx1, __shfl_xor_sync(0xffffffffu, rx1, 2));
        float mn0 = fmaxf(m0, rx0), mn1 = fmaxf(m1, rx1);
        float al0 = __expf(m0 - mn0), al1 = __expf(m1 - mn1);
        m0 = mn0; m1 = mn1;

        u32 prow0[8], prow1[8];
        float sum0 = 0.f, sum1 = 0.f;
        #pragma unroll
        for (int nt = 0; nt < 8; nt++) {
            float p00 = __expf(sc[nt][0] - mn0);
            float p01 = __expf(sc[nt][1] - mn0);
            float p10 = __expf(sc[nt][2] - mn1);
            float p11 = __expf(sc[nt][3] - mn1);
            sum0 += p00 + p01; sum1 += p10 + p11;
            prow0[nt] = bf2(p00, p01);
            prow1[nt] = bf2(p10, p11);
        }
        sum0 += __shfl_xor_sync(0xffffffffu, sum0, 1);
        sum0 += __shfl_xor_sync(0xffffffffu, sum0, 2);
        sum1 += __shfl_xor_sync(0xffffffffu, sum1, 1);
        sum1 += __shfl_xor_sync(0xffffffffu, sum1, 2);
        l0 = l0 * al0 + sum0;
        l1 = l1 * al1 + sum1;
        #pragma unroll
        for (int nt = 0; nt < 8; nt++) {
            oc[nt][0] *= al0; oc[nt][1] *= al0;
            oc[nt][2] *= al1; oc[nt][3] *= al1;
        }
        // P store: word for nt at perm 8qd+nt -> contiguous run, 2 uint4/row.
        *(uint4*)(sP + r0 * PR + 8 * qd)     = make_uint4(prow0[0], prow0[1], prow0[2], prow0[3]);
        *(uint4*)(sP + r0 * PR + 8 * qd + 4) = make_uint4(prow0[4], prow0[5], prow0[6], prow0[7]);
        *(uint4*)(sP + (r0 + 8) * PR + 8 * qd)     = make_uint4(prow1[0], prow1[1], prow1[2], prow1[3]);
        *(uint4*)(sP + (r0 + 8) * PR + 8 * qd + 4) = make_uint4(prow1[4], prow1[5], prow1[6], prow1[7]);
        __syncwarp();

        // PV: A = own P rows, B = V tiles.
        u32 pA0[8], pA1[8];
        #pragma unroll
        for (int u = 0; u < 2; u++) {
            uint4 x0 = *(const uint4*)(sP + r0 * PR + 8 * qd + 4 * u);
            uint4 x1 = *(const uint4*)(sP + (r0 + 8) * PR + 8 * qd + 4 * u);
            pA0[4*u] = x0.x; pA0[4*u+1] = x0.y; pA0[4*u+2] = x0.z; pA0[4*u+3] = x0.w;
            pA1[4*u] = x1.x; pA1[4*u+1] = x1.y; pA1[4*u+2] = x1.z; pA1[4*u+3] = x1.w;
        }
        #pragma unroll
        for (int nt = 0; nt < 8; nt++) {
            const u32* bp = sVc + (8 * nt + grp) * PR + 8 * qd;
            uint4 B0 = *(const uint4*)bp;
            uint4 B1 = *(const uint4*)(bp + 4);
            mma_bf16(oc[nt], pA0[0], pA1[0], pA0[1], pA1[1], B0.x, B0.y);
            mma_bf16(oc[nt], pA0[2], pA1[2], pA0[3], pA1[3], B0.z, B0.w);
            mma_bf16(oc[nt], pA0[4], pA1[4], pA0[5], pA1[5], B1.x, B1.y);
            mma_bf16(oc[nt], pA0[6], pA1[6], pA0[7], pA1[7], B1.z, B1.w);
        }

        // Stage prefetched tile into the alternate buffer.
        if (hasNext) {
            #pragma unroll
            for (int r = 0; r < 2; r++) {
                int idx = r * 256 + tid;
                int row = idx >> 3, q4 = (idx & 7) * 4;
                *(uint4*)(sKn + row * PR + q4) = pfK[r];
                *(uint4*)(sVn + row * PR + q4) = pfV[r];
            }
        }
        __syncthreads();
    }

    if (!FINAL) {
        size_t mlidx = (size_t)(part * B_ + b) * N4_ + qt * 128 + r0;
        #pragma unroll
        for (int nt = 0; nt < 8; nt++) {
            *(float2*)(g_po + mlidx * 64 + 8 * nt + 2 * qd) =
                make_float2(oc[nt][0], oc[nt][1]);
            *(float2*)(g_po + (mlidx + 8) * 64 + 8 * nt + 2 * qd) =
                make_float2(oc[nt][2], oc[nt][3]);
        }
        if (qd == 0) {
            g_m2[mlidx] = m0; g_l2[mlidx] = l0;
            g_m2[mlidx + 8] = m1; g_l2[mlidx + 8] = l1;
        }
    } else {
        // fp32 staging [128 q][64 c], pitch 66, then fused residual transpose.
        float* st = (float*)sm;
        float inv0 = 1.f / l0, inv1 = 1.f / l1;
        #pragma unroll
        for (int nt = 0; nt < 8; nt++) {
            *(float2*)(st + r0 * 66 + 8 * nt + 2 * qd) =
                make_float2(oc[nt][0] * inv0, oc[nt][1] * inv0);
            *(float2*)(st + (r0 + 8) * 66 + 8 * nt + 2 * qd) =
                make_float2(oc[nt][2] * inv1, oc[nt][3] * inv1);
        }
        __syncthreads();
        float gamma = gp[0];
        int n0 = qt * 128;
        #pragma unroll 4
        for (int r2 = 0; r2 < 32; r2++) {
            int idx = r2 * 256 + tid;
            int c = idx >> 7, nl = idx & 127;
            size_t ga = ((size_t)b * 64 + c) * (size_t)N_ + n0 + nl;
            outg[ga] = gamma * st[nl * 66 + c] + xr[ga];
        }
    }
}

// Merge split-K partials: exact flash combine -> g_o1 (fp32 n-major).
__global__ __launch_bounds__(256)
void combine_kernel()
{
    int idx = blockIdx.x * 256 + threadIdx.x;
    int row = idx >> 4, c4 = (idx & 15) * 4;
    float mv[SPLIT1], lv[SPLIT1];
    float M = -1e30f;
    #pragma unroll
    for (int p = 0; p < SPLIT1; p++) {
        mv[p] = g_m2[p * BN4 + row];
        lv[p] = g_l2[p * BN4 + row];
        M = fmaxf(M, mv[p]);
    }
    float w[SPLIT1], ltot = 0.f;
    #pragma unroll
    for (int p = 0; p < SPLIT1; p++) {
        w[p] = __expf(mv[p] - M);
        ltot += lv[p] * w[p];
    }
    float inv = 1.f / ltot;
    float4 acc = make_float4(0.f, 0.f, 0.f, 0.f);
    #pragma unroll
    for (int p = 0; p < SPLIT1; p++) {
        float4 a = *(const float4*)(g_po + ((size_t)p * BN4 + row) * 64 + c4);
        acc.x += a.x * w[p]; acc.y += a.y * w[p];
        acc.z += a.z * w[p]; acc.w += a.w * w[p];
    }
    *(float4*)(g_o1 + (size_t)row * 64 + c4) =
        make_float4(acc.x * inv, acc.y * inv, acc.z * inv, acc.w * inv);
}

// ---------------- Launch ----------------

extern "C" void kernel_launch(void* const* d_in, const int* in_sizes, int n_in,
                              void* d_out, int out_size)
{
    (void)in_sizes; (void)n_in; (void)out_size;
    const float* x     = (const float*)d_in[0];
    const float* w_q   = (const float*)d_in[1];
    const float* b_q   = (const float*)d_in[2];
    const float* w_K   = (const float*)d_in[3];
    const float* b_K   = (const float*)d_in[4];
    const float* w_V   = (const float*)d_in[5];
    const float* b_V   = (const float*)d_in[6];
    const float* w_Q   = (const float*)d_in[7];
    const float* b_Q   = (const float*)d_in[8];
    const float* w_k   = (const float*)d_in[9];
    const float* b_k   = (const float*)d_in[10];
    const float* w_v   = (const float*)d_in[11];
    const float* b_v   = (const float*)d_in[12];
    const float* gamma = (const float*)d_in[13];
    float* out = (float*)d_out;

    const int proj_smem = PROJ_SMEM_FLOATS * 4;   // 52480 B
    const int attn_smem = 512 * PR * 4;           // 73728 B

    cudaFuncSetAttribute(projA_kernel, cudaFuncAttributeMaxDynamicSharedMemorySize, proj_smem);
    cudaFuncSetAttribute(projP_kernel, cudaFuncAttributeMaxDynamicSharedMemorySize, proj_smem);
    cudaFuncSetAttribute(projC_kernel, cudaFuncAttributeMaxDynamicSharedMemorySize, proj_smem);
    cudaFuncSetAttribute(attn_kernel<false>, cudaFuncAttributeMaxDynamicSharedMemorySize, attn_smem);
    cudaFuncSetAttribute(attn_kernel<true>,  cudaFuncAttributeMaxDynamicSharedMemorySize, attn_smem);

    // Projections for stage 1 + stage 2 queries (bf16 perm outputs).
    projA_kernel<<<dim3(B_*N_/64, 3), 256, proj_smem>>>(x, w_K, b_K, w_V, b_V, w_Q, b_Q);
    projP_kernel<<<dim3(B_*N4_/64), 256, proj_smem>>>(x, w_q, b_q);

    // Stage 1 attention: split-K over 4 parts (8 x 8 x 4 = 256 CTAs), combine.
    attn_kernel<false><<<dim3(N4_/128, B_, SPLIT1), 256, attn_smem>>>(nullptr, nullptr, nullptr);
    combine_kernel<<<(BN4*16)/256, 256>>>();

    // Stage 2 projections from stage1 output.
    projC_kernel<<<dim3(B_*N4_/64, 2), 256, proj_smem>>>(w_k, b_k, w_v, b_v);

    // Stage 2 attention + residual epilogue (32 x 8 = 256 CTAs).
    attn_kernel<true><<<dim3(N_/128, B_), 256, attn_smem>>>(out, x, gamma);
}

// round 13
// speedup vs baseline: 6.5342x; 1.3896x over previous
#include <cuda_runtime.h>
#include <cstdint>
#include <cstddef>

#define B_  8
#define C_  64
#define N_  4096
#define N4_ 1024
#define SPLIT1 4
#define BN4 (B_*N4_)
#define PR 36

typedef unsigned long long u64;
typedef unsigned int u32;

// bf16 operands as bf16x2 words; per row 32 words over the 64-elt contraction
// dim, word w stored at perm p(w) = (w&3)*8 + (w>>2).
__device__ u32 g_K [B_*N_*32];          // (b,key)[32]     stage1 keys
__device__ u32 g_V [B_*C_*(N_/64)*32];  // (b,c,ktile)[32] stage1 values
__device__ u32 g_Q [B_*N_*32];          // (b,q)[32]       stage2 queries
__device__ u32 g_qp[B_*N4_*32];         // (b,j)[32]       stage1 pooled queries
__device__ u32 g_kp[B_*N4_*32];         // (b,j)[32]       stage2 keys
__device__ u32 g_vp[B_*C_*(N4_/64)*32]; // (b,c,ktile)[32] stage2 values
__device__ float g_po[SPLIT1*BN4*C_];   // split-K partials (unnormalized)
__device__ float g_m2[SPLIT1*BN4];
__device__ float g_l2[SPLIT1*BN4];

__device__ __forceinline__ u32 bf2(float lo, float hi) {
    u32 r; asm("cvt.rn.bf16x2.f32 %0, %1, %2;" : "=r"(r) : "f"(hi), "f"(lo)); return r;
}
__device__ __forceinline__ int permw(int w) { return (w & 3) * 8 + (w >> 2); }

__device__ __forceinline__ void mma_bf16(float c[4], u32 a0, u32 a1, u32 a2, u32 a3,
                                         u32 b0, u32 b1) {
    asm volatile(
        "mma.sync.aligned.m16n8k16.row.col.f32.bf16.bf16.f32 "
        "{%0,%1,%2,%3},{%4,%5,%6,%7},{%8,%9},{%0,%1,%2,%3};"
        : "+f"(c[0]), "+f"(c[1]), "+f"(c[2]), "+f"(c[3])
        : "r"(a0), "r"(a1), "r"(a2), "r"(a3), "r"(b0), "r"(b1));
}

// ================= bf16-MMA projection core ================================
// CTA = 128 positions x 64 outputs. 8 warps x 16 position-rows.
// sX [128 pos][PR] perm words over c_in; sW [64 cout][PR] perm words over c_in.
// D[pos][cout] in fp32 frags sc[8][4].

__device__ __forceinline__ void stage_W(const float* __restrict__ w,
                                        const float* __restrict__ bias,
                                        u32* sW, float* sb, int tid)
{
    for (int i = tid; i < 1024; i += 256) {
        int o = i >> 4, t = i & 15;
        float4 v = *(const float4*)(w + o * 64 + 4 * t);
        sW[o * PR + permw(2 * t)]     = bf2(v.x, v.y);
        sW[o * PR + permw(2 * t + 1)] = bf2(v.z, v.w);
    }
    if (tid < 64) sb[tid] = bias[tid];
}

__device__ __forceinline__ void proj_mma(const u32* sX, const u32* sW,
                                         float sc[8][4], int wid, int grp, int qd)
{
    int r0 = wid * 16 + grp;
    u32 a0[8], a1[8];
    #pragma unroll
    for (int u = 0; u < 2; u++) {
        uint4 x0 = *(const uint4*)(sX + r0 * PR + 8 * qd + 4 * u);
        uint4 x1 = *(const uint4*)(sX + (r0 + 8) * PR + 8 * qd + 4 * u);
        a0[4*u] = x0.x; a0[4*u+1] = x0.y; a0[4*u+2] = x0.z; a0[4*u+3] = x0.w;
        a1[4*u] = x1.x; a1[4*u+1] = x1.y; a1[4*u+2] = x1.z; a1[4*u+3] = x1.w;
    }
    #pragma unroll
    for (int nt = 0; nt < 8; nt++) {
        sc[nt][0] = 0.f; sc[nt][1] = 0.f; sc[nt][2] = 0.f; sc[nt][3] = 0.f;
        const u32* bp = sW + (8 * nt + grp) * PR + 8 * qd;
        uint4 B0 = *(const uint4*)bp;
        uint4 B1 = *(const uint4*)(bp + 4);
        mma_bf16(sc[nt], a0[0], a1[0], a0[1], a1[1], B0.x, B0.y);
        mma_bf16(sc[nt], a0[2], a1[2], a0[3], a1[3], B0.z, B0.w);
        mma_bf16(sc[nt], a0[4], a1[4], a0[5], a1[5], B1.x, B1.y);
        mma_bf16(sc[nt], a0[6], a1[6], a0[7], a1[7], B1.z, B1.w);
    }
}

// n-major perm store: rows = positions. Lane's 8 words land at perm 8qd..8qd+7.
__device__ __forceinline__ void store_nmaj(u32* __restrict__ dst,
                                           const float sc[8][4], const float* sb,
                                           int r0, int qd)
{
    u32 w0[8], w1[8];
    #pragma unroll
    for (int nt = 0; nt < 8; nt++) {
        float2 bb = *(const float2*)(sb + 8 * nt + 2 * qd);
        w0[nt] = bf2(sc[nt][0] + bb.x, sc[nt][1] + bb.y);
        w1[nt] = bf2(sc[nt][2] + bb.x, sc[nt][3] + bb.y);
    }
    *(uint4*)(dst + (size_t)r0 * 32 + 8 * qd)     = make_uint4(w0[0], w0[1], w0[2], w0[3]);
    *(uint4*)(dst + (size_t)r0 * 32 + 8 * qd + 4) = make_uint4(w0[4], w0[5], w0[6], w0[7]);
    *(uint4*)(dst + (size_t)(r0 + 8) * 32 + 8 * qd)     = make_uint4(w1[0], w1[1], w1[2], w1[3]);
    *(uint4*)(dst + (size_t)(r0 + 8) * 32 + 8 * qd + 4) = make_uint4(w1[4], w1[5], w1[6], w1[7]);
}

// c-major perm store (V): transpose via fp32 st [128 pos][67].
__device__ __forceinline__ void store_cmaj(u32* __restrict__ out, int NT, int ktbase,
                                           float* st, const float sc[8][4],
                                           const float* sb, int r0, int qd, int tid)
{
    __syncthreads();   // st may overlay sX/sW
    #pragma unroll
    for (int nt = 0; nt < 8; nt++) {
        float2 bb = *(const float2*)(sb + 8 * nt + 2 * qd);
        st[r0 * 67 + 8 * nt + 2 * qd]     = sc[nt][0] + bb.x;
        st[r0 * 67 + 8 * nt + 2 * qd + 1] = sc[nt][1] + bb.y;
        st[(r0 + 8) * 67 + 8 * nt + 2 * qd]     = sc[nt][2] + bb.x;
        st[(r0 + 8) * 67 + 8 * nt + 2 * qd + 1] = sc[nt][3] + bb.y;
    }
    __syncthreads();
    for (int i = tid; i < 4096; i += 256) {
        int w = i & 31, tile = (i >> 5) & 1, cout = i >> 6;
        float v0 = st[(tile * 64 + 2 * w) * 67 + cout];
        float v1 = st[(tile * 64 + 2 * w + 1) * 67 + cout];
        out[((size_t)cout * NT + ktbase + tile) * 32 + permw(w)] = bf2(v0, v1);
    }
}

// ---- K / V / Q projections from x (which = blockIdx.y: 0=K 1=V 2=Q) ----
#define PROJX_SMEM ((128*67 + 64) * 4)   // st overlays sX+sW; sb beyond st
__global__ __launch_bounds__(256)
void projX_kernel(const float* __restrict__ x,
                  const float* __restrict__ wK, const float* __restrict__ bK,
                  const float* __restrict__ wV, const float* __restrict__ bV,
                  const float* __restrict__ wQ, const float* __restrict__ bQ)
{
    extern __shared__ u32 sm[];
    u32* sX = sm;                       // 128*36
    u32* sW = sm + 128 * PR;            // 64*36
    float* st = (float*)sm;             // 128*67 (post-mma, V only)
    float* sb = (float*)(sm + 128 * 67);
    int which = blockIdx.y;
    int tid = threadIdx.x;
    const float* w  = which == 0 ? wK : (which == 1 ? wV : wQ);
    const float* bs = which == 0 ? bK : (which == 1 ? bV : bQ);
    stage_W(w, bs, sW, sb, tid);

    int gpos0 = blockIdx.x * 128;
    int b = gpos0 >> 12, n0 = gpos0 & (N_ - 1);
    const float* xb = x + (size_t)b * C_ * N_ + n0;
    #pragma unroll
    for (int it = 0; it < 2; it++) {
        int idx = it * 256 + tid;
        int pos = idx & 127, a = idx >> 7;   // lanes walk positions -> coalesced
        u32 wb[8];
        #pragma unroll
        for (int j = 0; j < 8; j++) {
            int ch = 8 * j + 2 * a;
            wb[j] = bf2(xb[(size_t)ch * N_ + pos], xb[(size_t)(ch + 1) * N_ + pos]);
        }
        *(uint4*)(sX + pos * PR + 8 * a)     = make_uint4(wb[0], wb[1], wb[2], wb[3]);
        *(uint4*)(sX + pos * PR + 8 * a + 4) = make_uint4(wb[4], wb[5], wb[6], wb[7]);
    }
    __syncthreads();

    int wid = tid >> 5, lane = tid & 31, grp = lane >> 2, qd = lane & 3;
    float sc[8][4];
    proj_mma(sX, sW, sc, wid, grp, qd);
    int r0 = wid * 16 + grp;
    if (which == 0)      store_nmaj(g_K + (size_t)gpos0 * 32, sc, sb, r0, qd);
    else if (which == 2) store_nmaj(g_Q + (size_t)gpos0 * 32, sc, sb, r0, qd);
    else store_cmaj(g_V + (size_t)b * 64 * 64 * 32, 64, n0 >> 6, st, sc, sb, r0, qd, tid);
}

// ---- Pooled q projection (pool commutes with 1x1 conv) ----
#define PROJP_SMEM ((128*PR + 64*PR + 64) * 4)
__global__ __launch_bounds__(256)
void projP_kernel(const float* __restrict__ x,
                  const float* __restrict__ wq, const float* __restrict__ bq)
{
    extern __shared__ u32 sm[];
    u32* sX = sm;
    u32* sW = sm + 128 * PR;
    float* sb = (float*)(sm + 128 * PR + 64 * PR);
    int tid = threadIdx.x;
    stage_W(wq, bq, sW, sb, tid);

    int gpos0 = blockIdx.x * 128;
    int b = gpos0 >> 10, j0 = gpos0 & (N4_ - 1);
    const float* xb = x + (size_t)b * C_ * N_;
    #pragma unroll
    for (int it = 0; it < 2; it++) {
        int idx = it * 256 + tid;
        int pos = idx & 127, a = idx >> 7;
        int jj = j0 + pos;
        size_t base = (size_t)(jj >> 5) * 128 + (jj & 31) * 2;
        u32 wb[8];
        #pragma unroll
        for (int j = 0; j < 8; j++) {
            int ch = 8 * j + 2 * a;
            const float* p0 = xb + (size_t)ch * N_ + base;
            const float* p1 = xb + (size_t)(ch + 1) * N_ + base;
            float v0 = 0.25f * (p0[0] + p0[1] + p0[64] + p0[65]);
            float v1 = 0.25f * (p1[0] + p1[1] + p1[64] + p1[65]);
            wb[j] = bf2(v0, v1);
        }
        *(uint4*)(sX + pos * PR + 8 * a)     = make_uint4(wb[0], wb[1], wb[2], wb[3]);
        *(uint4*)(sX + pos * PR + 8 * a + 4) = make_uint4(wb[4], wb[5], wb[6], wb[7]);
    }
    __syncthreads();

    int wid = tid >> 5, lane = tid & 31, grp = lane >> 2, qd = lane & 3;
    float sc[8][4];
    proj_mma(sX, sW, sc, wid, grp, qd);
    store_nmaj(g_qp + (size_t)gpos0 * 32, sc, sb, wid * 16 + grp, qd);
}

// ---- kp / vp projections with FUSED split-K combine (which: 0=kp 1=vp) ----
// smem: st (128*67) | sX | sW | sb | swt(128*4)
#define COMB_ST  0
#define COMB_SX  (128*67)
#define COMB_SW  (COMB_SX + 128*PR)
#define COMB_SB  (COMB_SW + 64*PR)
#define COMB_SWT (COMB_SB + 64)
#define PROJC_SMEM ((COMB_SWT + 512) * 4)
__global__ __launch_bounds__(256)
void projC_kernel(const float* __restrict__ wk, const float* __restrict__ bk,
                  const float* __restrict__ wv, const float* __restrict__ bv)
{
    extern __shared__ u32 sm[];
    float* st = (float*)sm;
    u32* sX = sm + COMB_SX;
    u32* sW = sm + COMB_SW;
    float* sb = (float*)(sm + COMB_SB);
    float* swt = (float*)(sm + COMB_SWT);
    int which = blockIdx.y;
    int tid = threadIdx.x;
    stage_W(which ? wv : wk, which ? bv : bk, sW, sb, tid);

    int gpos0 = blockIdx.x * 128;
    int b = gpos0 >> 10, j0 = gpos0 & (N4_ - 1);

    // Per-position combine weights (inv folded in).
    if (tid < 128) {
        int grow = gpos0 + tid;
        float mv[SPLIT1], lv[SPLIT1], M = -1e30f;
        #pragma unroll
        for (int p = 0; p < SPLIT1; p++) {
            mv[p] = g_m2[p * BN4 + grow];
            lv[p] = g_l2[p * BN4 + grow];
            M = fmaxf(M, mv[p]);
        }
        float wv_[SPLIT1], ls = 0.f;
        #pragma unroll
        for (int p = 0; p < SPLIT1; p++) { wv_[p] = __expf(mv[p] - M); ls += lv[p] * wv_[p]; }
        float inv = 1.f / ls;
        #pragma unroll
        for (int p = 0; p < SPLIT1; p++) swt[tid * 4 + p] = wv_[p] * inv;
    }
    __syncthreads();

    // Combined o1 into fp32 st [pos][67].
    for (int i = tid; i < 2048; i += 256) {
        int c4 = i & 15, pos = i >> 4;
        const float* wp = swt + pos * 4;
        float4 acc = make_float4(0.f, 0.f, 0.f, 0.f);
        #pragma unroll
        for (int p = 0; p < SPLIT1; p++) {
            float4 a = *(const float4*)(g_po + ((size_t)p * BN4 + gpos0 + pos) * 64 + 4 * c4);
            float wf = wp[p];
            acc.x += wf * a.x; acc.y += wf * a.y; acc.z += wf * a.z; acc.w += wf * a.w;
        }
        float* d = st + pos * 67 + 4 * c4;
        d[0] = acc.x; d[1] = acc.y; d[2] = acc.z; d[3] = acc.w;
    }
    __syncthreads();

    // sX (bf16 perm) from st.
    #pragma unroll
    for (int it = 0; it < 2; it++) {
        int idx = it * 256 + tid;
        int pos = idx & 127, a = idx >> 7;
        const float* row = st + pos * 67;
        u32 wb[8];
        #pragma unroll
        for (int j = 0; j < 8; j++) {
            int ch = 8 * j + 2 * a;
            wb[j] = bf2(row[ch], row[ch + 1]);
        }
        *(uint4*)(sX + pos * PR + 8 * a)     = make_uint4(wb[0], wb[1], wb[2], wb[3]);
        *(uint4*)(sX + pos * PR + 8 * a + 4) = make_uint4(wb[4], wb[5], wb[6], wb[7]);
    }
    __syncthreads();

    int wid = tid >> 5, lane = tid & 31, grp = lane >> 2, qd = lane & 3;
    float sc[8][4];
    proj_mma(sX, sW, sc, wid, grp, qd);
    int r0 = wid * 16 + grp;
    if (which == 0) store_nmaj(g_kp + (size_t)gpos0 * 32, sc, sb, r0, qd);
    else store_cmaj(g_vp + (size_t)b * 64 * 16 * 32, 16, j0 >> 6, st, sc, sb, r0, qd, tid);
}

// ================= bf16 m16n8k16 flash attention (unchanged R12 core) ======
template<bool FINAL>
__global__ __launch_bounds__(256, 2)
void attn_kernel(float* __restrict__ outg,
                 const float* __restrict__ xr,
                 const float* __restrict__ gp)
{
    constexpr int NKEY = FINAL ? 1024 : 4096;
    constexpr int NQ   = FINAL ? 4096 : 1024;
    constexpr int NT   = NKEY / 64;

    extern __shared__ u32 sm[];
    u32* sQ  = sm;                 // 128*36
    u32* sK0 = sQ  + 128 * PR;     // 64*36
    u32* sV0 = sK0 + 64 * PR;
    u32* sK1 = sV0 + 64 * PR;
    u32* sV1 = sK1 + 64 * PR;
    u32* sP  = sV1 + 64 * PR;      // 128*36

    int tid = threadIdx.x;
    int wid = tid >> 5, lane = tid & 31;
    int grp = lane >> 2, qd = lane & 3;
    int b = blockIdx.y, qt = blockIdx.x;
    int part = FINAL ? 0 : blockIdx.z;

    const u32* Qg = (FINAL ? g_Q  : g_qp) + ((size_t)b * NQ + qt * 128) * 32;
    const u32* Kg = (FINAL ? g_kp : g_K ) + (size_t)b * NKEY * 32;
    const u32* Vg = (FINAL ? g_vp : g_V ) + (size_t)b * C_ * NT * 32;

    int nkt = FINAL ? NT : NT / SPLIT1;
    int kt0 = part * nkt;

    #pragma unroll
    for (int r = 0; r < 4; r++) {
        int idx = r * 256 + tid;
        int row = idx >> 3, q4 = (idx & 7) * 4;
        *(uint4*)(sQ + row * PR + q4) = *(const uint4*)(Qg + (size_t)row * 32 + q4);
    }
    #pragma unroll
    for (int r = 0; r < 2; r++) {
        int idx = r * 256 + tid;
        int row = idx >> 3, q4 = (idx & 7) * 4;
        *(uint4*)(sK0 + row * PR + q4) =
            *(const uint4*)(Kg + ((size_t)kt0 * 64 + row) * 32 + q4);
        *(uint4*)(sV0 + row * PR + q4) =
            *(const uint4*)(Vg + ((size_t)row * NT + kt0) * 32 + q4);
    }
    __syncthreads();

    int r0 = wid * 16 + grp;
    u32 aQ0[8], aQ1[8];
    #pragma unroll
    for (int u = 0; u < 2; u++) {
        uint4 x0 = *(const uint4*)(sQ + r0 * PR + 8 * qd + 4 * u);
        uint4 x1 = *(const uint4*)(sQ + (r0 + 8) * PR + 8 * qd + 4 * u);
        aQ0[4*u] = x0.x; aQ0[4*u+1] = x0.y; aQ0[4*u+2] = x0.z; aQ0[4*u+3] = x0.w;
        aQ1[4*u] = x1.x; aQ1[4*u+1] = x1.y; aQ1[4*u+2] = x1.z; aQ1[4*u+3] = x1.w;
    }

    float m0 = -1e30f, m1 = -1e30f, l0 = 0.f, l1 = 0.f;
    float oc[8][4];
    #pragma unroll
    for (int nt = 0; nt < 8; nt++) {
        oc[nt][0] = 0.f; oc[nt][1] = 0.f; oc[nt][2] = 0.f; oc[nt][3] = 0.f;
    }

    for (int kk = 0; kk < nkt; kk++) {
        const u32* sKc = (kk & 1) ? sK1 : sK0;
        const u32* sVc = (kk & 1) ? sV1 : sV0;
        u32* sKn = (kk & 1) ? sK0 : sK1;
        u32* sVn = (kk & 1) ? sV0 : sV1;

        uint4 pfK[2], pfV[2];
        bool hasNext = (kk + 1 < nkt);
        if (hasNext) {
            int kt = kt0 + kk + 1;
            #pragma unroll
            for (int r = 0; r < 2; r++) {
                int idx = r * 256 + tid;
                int row = idx >> 3, q4 = (idx & 7) * 4;
                pfK[r] = *(const uint4*)(Kg + ((size_t)kt * 64 + row) * 32 + q4);
                pfV[r] = *(const uint4*)(Vg + ((size_t)row * NT + kt) * 32 + q4);
            }
        }

        float sc[8][4];
        #pragma unroll
        for (int nt = 0; nt < 8; nt++) {
            sc[nt][0] = 0.f; sc[nt][1] = 0.f; sc[nt][2] = 0.f; sc[nt][3] = 0.f;
            const u32* bp = sKc + (8 * nt + grp) * PR + 8 * qd;
            uint4 B0 = *(const uint4*)bp;
            uint4 B1 = *(const uint4*)(bp + 4);
            mma_bf16(sc[nt], aQ0[0], aQ1[0], aQ0[1], aQ1[1], B0.x, B0.y);
            mma_bf16(sc[nt], aQ0[2], aQ1[2], aQ0[3], aQ1[3], B0.z, B0.w);
            mma_bf16(sc[nt], aQ0[4], aQ1[4], aQ0[5], aQ1[5], B1.x, B1.y);
            mma_bf16(sc[nt], aQ0[6], aQ1[6], aQ0[7], aQ1[7], B1.z, B1.w);
        }

        float rx0 = -1e30f, rx1 = -1e30f;
        #pragma unroll
        for (int nt = 0; nt < 8; nt++) {
            rx0 = fmaxf(rx0, fmaxf(sc[nt][0], sc[nt][1]));
            rx1 = fmaxf(rx1, fmaxf(sc[nt][2], sc[nt][3]));
        }
        rx0 = fmaxf(rx0, __shfl_xor_sync(0xffffffffu, rx0, 1));
        rx0 = fmaxf(rx0, __shfl_xor_sync(0xffffffffu, rx0, 2));
        rx1 = fmaxf(rx1, __shfl_xor_sync(0xffffffffu, rx1, 1));
        rx1 = fmaxf(rx1, __shfl_xor_sync(0xffffffffu, rx1, 2));
        float mn0 = fmaxf(m0, rx0), mn1 = fmaxf(m1, rx1);
        float al0 = __expf(m0 - mn0), al1 = __expf(m1 - mn1);
        m0 = mn0; m1 = mn1;

        u32 prow0[8], prow1[8];
        float sum0 = 0.f, sum1 = 0.f;
        #pragma unroll
        for (int nt = 0; nt < 8; nt++) {
            float p00 = __expf(sc[nt][0] - mn0);
            float p01 = __expf(sc[nt][1] - mn0);
            float p10 = __expf(sc[nt][2] - mn1);
            float p11 = __expf(sc[nt][3] - mn1);
            sum0 += p00 + p01; sum1 += p10 + p11;
            prow0[nt] = bf2(p00, p01);
            prow1[nt] = bf2(p10, p11);
        }
        sum0 += __shfl_xor_sync(0xffffffffu, sum0, 1);
        sum0 += __shfl_xor_sync(0xffffffffu, sum0, 2);
        sum1 += __shfl_xor_sync(0xffffffffu, sum1, 1);
        sum1 += __shfl_xor_sync(0xffffffffu, sum1, 2);
        l0 = l0 * al0 + sum0;
        l1 = l1 * al1 + sum1;
        #pragma unroll
        for (int nt = 0; nt < 8; nt++) {
            oc[nt][0] *= al0; oc[nt][1] *= al0;
            oc[nt][2] *= al1; oc[nt][3] *= al1;
        }
        *(uint4*)(sP + r0 * PR + 8 * qd)     = make_uint4(prow0[0], prow0[1], prow0[2], prow0[3]);
        *(uint4*)(sP + r0 * PR + 8 * qd + 4) = make_uint4(prow0[4], prow0[5], prow0[6], prow0[7]);
        *(uint4*)(sP + (r0 + 8) * PR + 8 * qd)     = make_uint4(prow1[0], prow1[1], prow1[2], prow1[3]);
        *(uint4*)(sP + (r0 + 8) * PR + 8 * qd + 4) = make_uint4(prow1[4], prow1[5], prow1[6], prow1[7]);
        __syncwarp();

        u32 pA0[8], pA1[8];
        #pragma unroll
        for (int u = 0; u < 2; u++) {
            uint4 x0 = *(const uint4*)(sP + r0 * PR + 8 * qd + 4 * u);
            uint4 x1 = *(const uint4*)(sP + (r0 + 8) * PR + 8 * qd + 4 * u);
            pA0[4*u] = x0.x; pA0[4*u+1] = x0.y; pA0[4*u+2] = x0.z; pA0[4*u+3] = x0.w;
            pA1[4*u] = x1.x; pA1[4*u+1] = x1.y; pA1[4*u+2] = x1.z; pA1[4*u+3] = x1.w;
        }
        #pragma unroll
        for (int nt = 0; nt < 8; nt++) {
            const u32* bp = sVc + (8 * nt + grp) * PR + 8 * qd;
            uint4 B0 = *(const uint4*)bp;
            uint4 B1 = *(const uint4*)(bp + 4);
            mma_bf16(oc[nt], pA0[0], pA1[0], pA0[1], pA1[1], B0.x, B0.y);
            mma_bf16(oc[nt], pA0[2], pA1[2], pA0[3], pA1[3], B0.z, B0.w);
            mma_bf16(oc[nt], pA0[4], pA1[4], pA0[5], pA1[5], B1.x, B1.y);
            mma_bf16(oc[nt], pA0[6], pA1[6], pA0[7], pA1[7], B1.z, B1.w);
        }

        if (hasNext) {
            #pragma unroll
            for (int r = 0; r < 2; r++) {
                int idx = r * 256 + tid;
                int row = idx >> 3, q4 = (idx & 7) * 4;
                *(uint4*)(sKn + row * PR + q4) = pfK[r];
                *(uint4*)(sVn + row * PR + q4) = pfV[r];
            }
        }
        __syncthreads();
    }

    if (!FINAL) {
        size_t mlidx = (size_t)(part * B_ + b) * N4_ + qt * 128 + r0;
        #pragma unroll
        for (int nt = 0; nt < 8; nt++) {
            *(float2*)(g_po + mlidx * 64 + 8 * nt + 2 * qd) =
                make_float2(oc[nt][0], oc[nt][1]);
            *(float2*)(g_po + (mlidx + 8) * 64 + 8 * nt + 2 * qd) =
                make_float2(oc[nt][2], oc[nt][3]);
        }
        if (qd == 0) {
            g_m2[mlidx] = m0; g_l2[mlidx] = l0;
            g_m2[mlidx + 8] = m1; g_l2[mlidx + 8] = l1;
        }
    } else {
        float* st = (float*)sm;
        float inv0 = 1.f / l0, inv1 = 1.f / l1;
        #pragma unroll
        for (int nt = 0; nt < 8; nt++) {
            *(float2*)(st + r0 * 66 + 8 * nt + 2 * qd) =
                make_float2(oc[nt][0] * inv0, oc[nt][1] * inv0);
            *(float2*)(st + (r0 + 8) * 66 + 8 * nt + 2 * qd) =
                make_float2(oc[nt][2] * inv1, oc[nt][3] * inv1);
        }
        __syncthreads();
        float gamma = gp[0];
        int n0 = qt * 128;
        #pragma unroll 4
        for (int r2 = 0; r2 < 32; r2++) {
            int idx = r2 * 256 + tid;
            int c = idx >> 7, nl = idx & 127;
            size_t ga = ((size_t)b * 64 + c) * (size_t)N_ + n0 + nl;
            outg[ga] = gamma * st[nl * 66 + c] + xr[ga];
        }
    }
}

// ---------------- Launch ----------------

extern "C" void kernel_launch(void* const* d_in, const int* in_sizes, int n_in,
                              void* d_out, int out_size)
{
    (void)in_sizes; (void)n_in; (void)out_size;
    const float* x     = (const float*)d_in[0];
    const float* w_q   = (const float*)d_in[1];
    const float* b_q   = (const float*)d_in[2];
    const float* w_K   = (const float*)d_in[3];
    const float* b_K   = (const float*)d_in[4];
    const float* w_V   = (const float*)d_in[5];
    const float* b_V   = (const float*)d_in[6];
    const float* w_Q   = (const float*)d_in[7];
    const float* b_Q   = (const float*)d_in[8];
    const float* w_k   = (const float*)d_in[9];
    const float* b_k   = (const float*)d_in[10];
    const float* w_v   = (const float*)d_in[11];
    const float* b_v   = (const float*)d_in[12];
    const float* gamma = (const float*)d_in[13];
    float* out = (float*)d_out;

    const int attn_smem = 512 * PR * 4;   // 73728 B

    cudaFuncSetAttribute(projX_kernel, cudaFuncAttributeMaxDynamicSharedMemorySize, PROJX_SMEM);
    cudaFuncSetAttribute(projP_kernel, cudaFuncAttributeMaxDynamicSharedMemorySize, PROJP_SMEM);
    cudaFuncSetAttribute(projC_kernel, cudaFuncAttributeMaxDynamicSharedMemorySize, PROJC_SMEM);
    cudaFuncSetAttribute(attn_kernel<false>, cudaFuncAttributeMaxDynamicSharedMemorySize, attn_smem);
    cudaFuncSetAttribute(attn_kernel<true>,  cudaFuncAttributeMaxDynamicSharedMemorySize, attn_smem);

    // Projections (bf16 tensor-core), emitting attention-ready perm layouts.
    projX_kernel<<<dim3(B_*N_/128, 3), 256, PROJX_SMEM>>>(x, w_K, b_K, w_V, b_V, w_Q, b_Q);
    projP_kernel<<<B_*N4_/128, 256, PROJP_SMEM>>>(x, w_q, b_q);

    // Stage 1 attention: split-K over 4 parts (8 x 8 x 4 = 256 CTAs).
    attn_kernel<false><<<dim3(N4_/128, B_, SPLIT1), 256, attn_smem>>>(nullptr, nullptr, nullptr);

    // Stage 2 projections with fused split-K combine.
    projC_kernel<<<dim3(BN4/128, 2), 256, PROJC_SMEM>>>(w_k, b_k, w_v, b_v);

    // Stage 2 attention + residual epilogue (32 x 8 = 256 CTAs).
    attn_kernel<true><<<dim3(N_/128, B_), 256, attn_smem>>>(out, x, gamma);
}

// round 14
// speedup vs baseline: 7.3515x; 1.1251x over previous
#include <cuda_runtime.h>
#include <cstdint>
#include <cstddef>

#define B_  8
#define C_  64
#define N_  4096
#define N4_ 1024
#define SPLIT1 4
#define BN4 (B_*N4_)
#define PR 36
#define LOG2E 1.4426950408889634f

typedef unsigned long long u64;
typedef unsigned int u32;

// bf16 operands as bf16x2 words; per row 32 words over the 64-elt contraction
// dim, word w stored at perm p(w) = (w&3)*8 + (w>>2).
__device__ u32 g_K [B_*N_*32];          // (b,key)[32]     stage1 keys
__device__ u32 g_V [B_*C_*(N_/64)*32];  // (b,c,ktile)[32] stage1 values
__device__ u32 g_Q [B_*N_*32];          // (b,q)[32]       stage2 queries (pre-scaled by log2e)
__device__ u32 g_qp[B_*N4_*32];         // (b,j)[32]       stage1 pooled queries (pre-scaled)
__device__ u32 g_kp[B_*N4_*32];         // (b,j)[32]       stage2 keys
__device__ u32 g_vp[B_*C_*(N4_/64)*32]; // (b,c,ktile)[32] stage2 values
__device__ float g_po[SPLIT1*BN4*C_];   // split-K partials (unnormalized)
__device__ float g_m2[SPLIT1*BN4];
__device__ float g_l2[SPLIT1*BN4];

__device__ __forceinline__ u32 bf2(float lo, float hi) {
    u32 r; asm("cvt.rn.bf16x2.f32 %0, %1, %2;" : "=r"(r) : "f"(hi), "f"(lo)); return r;
}
__device__ __forceinline__ float ex2(float x) {
    float r; asm("ex2.approx.f32 %0, %1;" : "=f"(r) : "f"(x)); return r;
}
__device__ __forceinline__ int permw(int w) { return (w & 3) * 8 + (w >> 2); }

__device__ __forceinline__ void cpa16(u32* dst, const u32* src) {
    u32 d = (u32)__cvta_generic_to_shared(dst);
    asm volatile("cp.async.ca.shared.global [%0], [%1], 16;" :: "r"(d), "l"(src));
}
#define CP_COMMIT() asm volatile("cp.async.commit_group;" ::: "memory")
#define CP_WAIT0()  asm volatile("cp.async.wait_group 0;" ::: "memory")

__device__ __forceinline__ void mma_bf16(float c[4], u32 a0, u32 a1, u32 a2, u32 a3,
                                         u32 b0, u32 b1) {
    asm volatile(
        "mma.sync.aligned.m16n8k16.row.col.f32.bf16.bf16.f32 "
        "{%0,%1,%2,%3},{%4,%5,%6,%7},{%8,%9},{%0,%1,%2,%3};"
        : "+f"(c[0]), "+f"(c[1]), "+f"(c[2]), "+f"(c[3])
        : "r"(a0), "r"(a1), "r"(a2), "r"(a3), "r"(b0), "r"(b1));
}

// ================= bf16-MMA projection core ================================
// CTA = 128 positions x 64 outputs. 8 warps x 16 position-rows.

__device__ __forceinline__ void stage_W(const float* __restrict__ w,
                                        const float* __restrict__ bias,
                                        u32* sW, float* sb, int tid, float scale)
{
    for (int i = tid; i < 1024; i += 256) {
        int o = i >> 4, t = i & 15;
        float4 v = *(const float4*)(w + o * 64 + 4 * t);
        sW[o * PR + permw(2 * t)]     = bf2(v.x * scale, v.y * scale);
        sW[o * PR + permw(2 * t + 1)] = bf2(v.z * scale, v.w * scale);
    }
    if (tid < 64) sb[tid] = bias[tid] * scale;
}

__device__ __forceinline__ void proj_mma(const u32* sX, const u32* sW,
                                         float sc[8][4], int wid, int grp, int qd)
{
    int r0 = wid * 16 + grp;
    u32 a0[8], a1[8];
    #pragma unroll
    for (int u = 0; u < 2; u++) {
        uint4 x0 = *(const uint4*)(sX + r0 * PR + 8 * qd + 4 * u);
        uint4 x1 = *(const uint4*)(sX + (r0 + 8) * PR + 8 * qd + 4 * u);
        a0[4*u] = x0.x; a0[4*u+1] = x0.y; a0[4*u+2] = x0.z; a0[4*u+3] = x0.w;
        a1[4*u] = x1.x; a1[4*u+1] = x1.y; a1[4*u+2] = x1.z; a1[4*u+3] = x1.w;
    }
    #pragma unroll
    for (int nt = 0; nt < 8; nt++) {
        sc[nt][0] = 0.f; sc[nt][1] = 0.f; sc[nt][2] = 0.f; sc[nt][3] = 0.f;
        const u32* bp = sW + (8 * nt + grp) * PR + 8 * qd;
        uint4 B0 = *(const uint4*)bp;
        uint4 B1 = *(const uint4*)(bp + 4);
        mma_bf16(sc[nt], a0[0], a1[0], a0[1], a1[1], B0.x, B0.y);
        mma_bf16(sc[nt], a0[2], a1[2], a0[3], a1[3], B0.z, B0.w);
        mma_bf16(sc[nt], a0[4], a1[4], a0[5], a1[5], B1.x, B1.y);
        mma_bf16(sc[nt], a0[6], a1[6], a0[7], a1[7], B1.z, B1.w);
    }
}

__device__ __forceinline__ void store_nmaj(u32* __restrict__ dst,
                                           const float sc[8][4], const float* sb,
                                           int r0, int qd)
{
    u32 w0[8], w1[8];
    #pragma unroll
    for (int nt = 0; nt < 8; nt++) {
        float2 bb = *(const float2*)(sb + 8 * nt + 2 * qd);
        w0[nt] = bf2(sc[nt][0] + bb.x, sc[nt][1] + bb.y);
        w1[nt] = bf2(sc[nt][2] + bb.x, sc[nt][3] + bb.y);
    }
    *(uint4*)(dst + (size_t)r0 * 32 + 8 * qd)     = make_uint4(w0[0], w0[1], w0[2], w0[3]);
    *(uint4*)(dst + (size_t)r0 * 32 + 8 * qd + 4) = make_uint4(w0[4], w0[5], w0[6], w0[7]);
    *(uint4*)(dst + (size_t)(r0 + 8) * 32 + 8 * qd)     = make_uint4(w1[0], w1[1], w1[2], w1[3]);
    *(uint4*)(dst + (size_t)(r0 + 8) * 32 + 8 * qd + 4) = make_uint4(w1[4], w1[5], w1[6], w1[7]);
}

// c-major perm store (V): transpose via fp32 st [128 pos][67].
__device__ __forceinline__ void store_cmaj(u32* __restrict__ out, int NT, int ktbase,
                                           float* st, const float sc[8][4],
                                           const float* sb, int r0, int qd, int tid)
{
    __syncthreads();
    #pragma unroll
    for (int nt = 0; nt < 8; nt++) {
        float2 bb = *(const float2*)(sb + 8 * nt + 2 * qd);
        st[r0 * 67 + 8 * nt + 2 * qd]     = sc[nt][0] + bb.x;
        st[r0 * 67 + 8 * nt + 2 * qd + 1] = sc[nt][1] + bb.y;
        st[(r0 + 8) * 67 + 8 * nt + 2 * qd]     = sc[nt][2] + bb.x;
        st[(r0 + 8) * 67 + 8 * nt + 2 * qd + 1] = sc[nt][3] + bb.y;
    }
    __syncthreads();
    for (int i = tid; i < 4096; i += 256) {
        int w = i & 31, tile = (i >> 5) & 1, cout = i >> 6;
        float v0 = st[(tile * 64 + 2 * w) * 67 + cout];
        float v1 = st[(tile * 64 + 2 * w + 1) * 67 + cout];
        out[((size_t)cout * NT + ktbase + tile) * 32 + permw(w)] = bf2(v0, v1);
    }
}

// ---- K / V / Q projections from x (which = blockIdx.y: 0=K 1=V 2=Q) ----
#define PROJX_SMEM ((128*67 + 64) * 4)
__global__ __launch_bounds__(256)
void projX_kernel(const float* __restrict__ x,
                  const float* __restrict__ wK, const float* __restrict__ bK,
                  const float* __restrict__ wV, const float* __restrict__ bV,
                  const float* __restrict__ wQ, const float* __restrict__ bQ)
{
    extern __shared__ u32 sm[];
    u32* sX = sm;                       // 128*36
    u32* sW = sm + 128 * PR;            // 64*36
    float* st = (float*)sm;             // 128*67 (post-mma, V only)
    float* sb = (float*)(sm + 128 * 67);
    int which = blockIdx.y;
    int tid = threadIdx.x;
    const float* w  = which == 0 ? wK : (which == 1 ? wV : wQ);
    const float* bs = which == 0 ? bK : (which == 1 ? bV : bQ);
    stage_W(w, bs, sW, sb, tid, which == 2 ? LOG2E : 1.0f);

    int gpos0 = blockIdx.x * 128;
    int b = gpos0 >> 12, n0 = gpos0 & (N_ - 1);
    const float* xb = x + (size_t)b * C_ * N_ + n0;
    #pragma unroll
    for (int it = 0; it < 2; it++) {
        int idx = it * 256 + tid;
        int pos = idx & 127, a = idx >> 7;
        u32 wb[8];
        #pragma unroll
        for (int j = 0; j < 8; j++) {
            int ch = 8 * j + 2 * a;
            wb[j] = bf2(xb[(size_t)ch * N_ + pos], xb[(size_t)(ch + 1) * N_ + pos]);
        }
        *(uint4*)(sX + pos * PR + 8 * a)     = make_uint4(wb[0], wb[1], wb[2], wb[3]);
        *(uint4*)(sX + pos * PR + 8 * a + 4) = make_uint4(wb[4], wb[5], wb[6], wb[7]);
    }
    __syncthreads();

    int wid = tid >> 5, lane = tid & 31, grp = lane >> 2, qd = lane & 3;
    float sc[8][4];
    proj_mma(sX, sW, sc, wid, grp, qd);
    int r0 = wid * 16 + grp;
    if (which == 0)      store_nmaj(g_K + (size_t)gpos0 * 32, sc, sb, r0, qd);
    else if (which == 2) store_nmaj(g_Q + (size_t)gpos0 * 32, sc, sb, r0, qd);
    else store_cmaj(g_V + (size_t)b * 64 * 64 * 32, 64, n0 >> 6, st, sc, sb, r0, qd, tid);
}

// ---- Pooled q projection (pool commutes with 1x1 conv); log2e folded ----
#define PROJP_SMEM ((128*PR + 64*PR + 64) * 4)
__global__ __launch_bounds__(256)
void projP_kernel(const float* __restrict__ x,
                  const float* __restrict__ wq, const float* __restrict__ bq)
{
    extern __shared__ u32 sm[];
    u32* sX = sm;
    u32* sW = sm + 128 * PR;
    float* sb = (float*)(sm + 128 * PR + 64 * PR);
    int tid = threadIdx.x;
    stage_W(wq, bq, sW, sb, tid, LOG2E);

    int gpos0 = blockIdx.x * 128;
    int b = gpos0 >> 10, j0 = gpos0 & (N4_ - 1);
    const float* xb = x + (size_t)b * C_ * N_;
    #pragma unroll
    for (int it = 0; it < 2; it++) {
        int idx = it * 256 + tid;
        int pos = idx & 127, a = idx >> 7;
        int jj = j0 + pos;
        size_t base = (size_t)(jj >> 5) * 128 + (jj & 31) * 2;
        u32 wb[8];
        #pragma unroll
        for (int j = 0; j < 8; j++) {
            int ch = 8 * j + 2 * a;
            const float* p0 = xb + (size_t)ch * N_ + base;
            const float* p1 = xb + (size_t)(ch + 1) * N_ + base;
            float v0 = 0.25f * (p0[0] + p0[1] + p0[64] + p0[65]);
            float v1 = 0.25f * (p1[0] + p1[1] + p1[64] + p1[65]);
            wb[j] = bf2(v0, v1);
        }
        *(uint4*)(sX + pos * PR + 8 * a)     = make_uint4(wb[0], wb[1], wb[2], wb[3]);
        *(uint4*)(sX + pos * PR + 8 * a + 4) = make_uint4(wb[4], wb[5], wb[6], wb[7]);
    }
    __syncthreads();

    int wid = tid >> 5, lane = tid & 31, grp = lane >> 2, qd = lane & 3;
    float sc[8][4];
    proj_mma(sX, sW, sc, wid, grp, qd);
    store_nmaj(g_qp + (size_t)gpos0 * 32, sc, sb, wid * 16 + grp, qd);
}

// ---- kp / vp projections with FUSED split-K combine (which: 0=kp 1=vp) ----
#define COMB_SX  (128*67)
#define COMB_SW  (COMB_SX + 128*PR)
#define COMB_SB  (COMB_SW + 64*PR)
#define COMB_SWT (COMB_SB + 64)
#define PROJC_SMEM ((COMB_SWT + 512) * 4)
__global__ __launch_bounds__(256)
void projC_kernel(const float* __restrict__ wk, const float* __restrict__ bk,
                  const float* __restrict__ wv, const float* __restrict__ bv)
{
    extern __shared__ u32 sm[];
    float* st = (float*)sm;             // 128*67 (vp transpose only)
    u32* sX = sm + COMB_SX;
    u32* sW = sm + COMB_SW;
    float* sb = (float*)(sm + COMB_SB);
    float* swt = (float*)(sm + COMB_SWT);
    int which = blockIdx.y;
    int tid = threadIdx.x;
    stage_W(which ? wv : wk, which ? bv : bk, sW, sb, tid, 1.0f);

    int gpos0 = blockIdx.x * 128;
    int b = gpos0 >> 10, j0 = gpos0 & (N4_ - 1);

    // Per-position combine weights (inv folded in).
    if (tid < 128) {
        int grow = gpos0 + tid;
        float mv[SPLIT1], lv[SPLIT1], M = -1e30f;
        #pragma unroll
        for (int p = 0; p < SPLIT1; p++) {
            mv[p] = g_m2[p * BN4 + grow];
            lv[p] = g_l2[p * BN4 + grow];
            M = fmaxf(M, mv[p]);
        }
        float wv_[SPLIT1], ls = 0.f;
        #pragma unroll
        for (int p = 0; p < SPLIT1; p++) { wv_[p] = ex2(mv[p] - M); ls += lv[p] * wv_[p]; }
        float inv = 1.f / ls;
        #pragma unroll
        for (int p = 0; p < SPLIT1; p++) swt[tid * 4 + p] = wv_[p] * inv;
    }
    __syncthreads();

    // Combine partials, write bf16 perm sX DIRECTLY (no fp32 staging pass).
    for (int i = tid; i < 2048; i += 256) {
        int c4 = i & 15, pos = i >> 4;
        const float* wp = swt + pos * 4;
        float4 acc = make_float4(0.f, 0.f, 0.f, 0.f);
        #pragma unroll
        for (int p = 0; p < SPLIT1; p++) {
            float4 a = *(const float4*)(g_po + ((size_t)p * BN4 + gpos0 + pos) * 64 + 4 * c4);
            float wf = wp[p];
            acc.x += wf * a.x; acc.y += wf * a.y; acc.z += wf * a.z; acc.w += wf * a.w;
        }
        sX[pos * PR + permw(2 * c4)]     = bf2(acc.x, acc.y);
        sX[pos * PR + permw(2 * c4 + 1)] = bf2(acc.z, acc.w);
    }
    __syncthreads();

    int wid = tid >> 5, lane = tid & 31, grp = lane >> 2, qd = lane & 3;
    float sc[8][4];
    proj_mma(sX, sW, sc, wid, grp, qd);
    int r0 = wid * 16 + grp;
    if (which == 0) store_nmaj(g_kp + (size_t)gpos0 * 32, sc, sb, r0, qd);
    else store_cmaj(g_vp + (size_t)b * 64 * 16 * 32, 16, j0 >> 6, st, sc, sb, r0, qd, tid);
}

// ================= bf16 m16n8k16 flash attention ===========================
// CTA = 128 q-rows, 8 warps x 16 q-rows, 64-key tiles, double-buffered K/V
// via cp.async. Scores arrive in log2 domain (q pre-scaled by log2e).
// PV A-fragments come DIRECTLY from the softmax registers (prow) — the S-output
// C-frag layout equals the PV A-frag layout word-for-word; no P smem roundtrip.

template<bool FINAL>
__global__ __launch_bounds__(256, 2)
void attn_kernel(float* __restrict__ outg,
                 const float* __restrict__ xr,
                 const float* __restrict__ gp)
{
    constexpr int NKEY = FINAL ? 1024 : 4096;
    constexpr int NQ   = FINAL ? 4096 : 1024;
    constexpr int NT   = NKEY / 64;

    extern __shared__ u32 sm[];
    u32* sQ  = sm;                 // 128*36
    u32* sK0 = sQ  + 128 * PR;     // 64*36
    u32* sV0 = sK0 + 64 * PR;
    u32* sK1 = sV0 + 64 * PR;
    u32* sV1 = sK1 + 64 * PR;      // total 384*36 words

    int tid = threadIdx.x;
    int wid = tid >> 5, lane = tid & 31;
    int grp = lane >> 2, qd = lane & 3;
    int b = blockIdx.y, qt = blockIdx.x;
    int part = FINAL ? 0 : blockIdx.z;

    const u32* Qg = (FINAL ? g_Q  : g_qp) + ((size_t)b * NQ + qt * 128) * 32;
    const u32* Kg = (FINAL ? g_kp : g_K ) + (size_t)b * NKEY * 32;
    const u32* Vg = (FINAL ? g_vp : g_V ) + (size_t)b * C_ * NT * 32;

    int nkt = FINAL ? NT : NT / SPLIT1;
    int kt0 = part * nkt;

    #pragma unroll
    for (int r = 0; r < 4; r++) {
        int idx = r * 256 + tid;
        int row = idx >> 3, q4 = (idx & 7) * 4;
        *(uint4*)(sQ + row * PR + q4) = *(const uint4*)(Qg + (size_t)row * 32 + q4);
    }
    #pragma unroll
    for (int r = 0; r < 2; r++) {
        int idx = r * 256 + tid;
        int row = idx >> 3, q4 = (idx & 7) * 4;
        *(uint4*)(sK0 + row * PR + q4) =
            *(const uint4*)(Kg + ((size_t)kt0 * 64 + row) * 32 + q4);
        *(uint4*)(sV0 + row * PR + q4) =
            *(const uint4*)(Vg + ((size_t)row * NT + kt0) * 32 + q4);
    }
    __syncthreads();

    int r0 = wid * 16 + grp;
    u32 aQ0[8], aQ1[8];
    #pragma unroll
    for (int u = 0; u < 2; u++) {
        uint4 x0 = *(const uint4*)(sQ + r0 * PR + 8 * qd + 4 * u);
        uint4 x1 = *(const uint4*)(sQ + (r0 + 8) * PR + 8 * qd + 4 * u);
        aQ0[4*u] = x0.x; aQ0[4*u+1] = x0.y; aQ0[4*u+2] = x0.z; aQ0[4*u+3] = x0.w;
        aQ1[4*u] = x1.x; aQ1[4*u+1] = x1.y; aQ1[4*u+2] = x1.z; aQ1[4*u+3] = x1.w;
    }

    float m0 = -1e30f, m1 = -1e30f, l0 = 0.f, l1 = 0.f;
    float oc[8][4];
    #pragma unroll
    for (int nt = 0; nt < 8; nt++) {
        oc[nt][0] = 0.f; oc[nt][1] = 0.f; oc[nt][2] = 0.f; oc[nt][3] = 0.f;
    }

    for (int kk = 0; kk < nkt; kk++) {
        const u32* sKc = (kk & 1) ? sK1 : sK0;
        const u32* sVc = (kk & 1) ? sV1 : sV0;
        u32* sKn = (kk & 1) ? sK0 : sK1;
        u32* sVn = (kk & 1) ? sV0 : sV1;

        bool hasNext = (kk + 1 < nkt);
        if (hasNext) {
            int kt = kt0 + kk + 1;
            #pragma unroll
            for (int r = 0; r < 2; r++) {
                int idx = r * 256 + tid;
                int row = idx >> 3, q4 = (idx & 7) * 4;
                cpa16(sKn + row * PR + q4, Kg + ((size_t)kt * 64 + row) * 32 + q4);
                cpa16(sVn + row * PR + q4, Vg + ((size_t)row * NT + kt) * 32 + q4);
            }
            CP_COMMIT();
        }

        // S = Q K^T (log2 domain).
        float sc[8][4];
        #pragma unroll
        for (int nt = 0; nt < 8; nt++) {
            sc[nt][0] = 0.f; sc[nt][1] = 0.f; sc[nt][2] = 0.f; sc[nt][3] = 0.f;
            const u32* bp = sKc + (8 * nt + grp) * PR + 8 * qd;
            uint4 B0 = *(const uint4*)bp;
            uint4 B1 = *(const uint4*)(bp + 4);
            mma_bf16(sc[nt], aQ0[0], aQ1[0], aQ0[1], aQ1[1], B0.x, B0.y);
            mma_bf16(sc[nt], aQ0[2], aQ1[2], aQ0[3], aQ1[3], B0.z, B0.w);
            mma_bf16(sc[nt], aQ0[4], aQ1[4], aQ0[5], aQ1[5], B1.x, B1.y);
            mma_bf16(sc[nt], aQ0[6], aQ1[6], aQ0[7], aQ1[7], B1.z, B1.w);
        }

        // Online softmax; p = exp2(s - m) directly.
        float rx0 = -1e30f, rx1 = -1e30f;
        #pragma unroll
        for (int nt = 0; nt < 8; nt++) {
            rx0 = fmaxf(rx0, fmaxf(sc[nt][0], sc[nt][1]));
            rx1 = fmaxf(rx1, fmaxf(sc[nt][2], sc[nt][3]));
        }
        rx0 = fmaxf(rx0, __shfl_xor_sync(0xffffffffu, rx0, 1));
        rx0 = fmaxf(rx0, __shfl_xor_sync(0xffffffffu, rx0, 2));
        rx1 = fmaxf(rx1, __shfl_xor_sync(0xffffffffu, rx1, 1));
        rx1 = fmaxf(rx1, __shfl_xor_sync(0xffffffffu, rx1, 2));
        float mn0 = fmaxf(m0, rx0), mn1 = fmaxf(m1, rx1);
        float al0 = ex2(m0 - mn0), al1 = ex2(m1 - mn1);
        m0 = mn0; m1 = mn1;

        u32 prow0[8], prow1[8];
        float sum0 = 0.f, sum1 = 0.f;
        #pragma unroll
        for (int nt = 0; nt < 8; nt++) {
            float p00 = ex2(sc[nt][0] - mn0);
            float p01 = ex2(sc[nt][1] - mn0);
            float p10 = ex2(sc[nt][2] - mn1);
            float p11 = ex2(sc[nt][3] - mn1);
            sum0 += p00 + p01; sum1 += p10 + p11;
            prow0[nt] = bf2(p00, p01);
            prow1[nt] = bf2(p10, p11);
        }
        sum0 += __shfl_xor_sync(0xffffffffu, sum0, 1);
        sum0 += __shfl_xor_sync(0xffffffffu, sum0, 2);
        sum1 += __shfl_xor_sync(0xffffffffu, sum1, 1);
        sum1 += __shfl_xor_sync(0xffffffffu, sum1, 2);
        l0 = l0 * al0 + sum0;
        l1 = l1 * al1 + sum1;
        #pragma unroll
        for (int nt = 0; nt < 8; nt++) {
            oc[nt][0] *= al0; oc[nt][1] *= al0;
            oc[nt][2] *= al1; oc[nt][3] *= al1;
        }

        // PV: A-frags are prow0/prow1 directly (same thread-data mapping).
        #pragma unroll
        for (int nt = 0; nt < 8; nt++) {
            const u32* bp = sVc + (8 * nt + grp) * PR + 8 * qd;
            uint4 B0 = *(const uint4*)bp;
            uint4 B1 = *(const uint4*)(bp + 4);
            mma_bf16(oc[nt], prow0[0], prow1[0], prow0[1], prow1[1], B0.x, B0.y);
            mma_bf16(oc[nt], prow0[2], prow1[2], prow0[3], prow1[3], B0.z, B0.w);
            mma_bf16(oc[nt], prow0[4], prow1[4], prow0[5], prow1[5], B1.x, B1.y);
            mma_bf16(oc[nt], prow0[6], prow1[6], prow0[7], prow1[7], B1.z, B1.w);
        }

        if (hasNext) CP_WAIT0();
        __syncthreads();
    }

    if (!FINAL) {
        size_t mlidx = (size_t)(part * B_ + b) * N4_ + qt * 128 + r0;
        #pragma unroll
        for (int nt = 0; nt < 8; nt++) {
            *(float2*)(g_po + mlidx * 64 + 8 * nt + 2 * qd) =
                make_float2(oc[nt][0], oc[nt][1]);
            *(float2*)(g_po + (mlidx + 8) * 64 + 8 * nt + 2 * qd) =
                make_float2(oc[nt][2], oc[nt][3]);
        }
        if (qd == 0) {
            g_m2[mlidx] = m0; g_l2[mlidx] = l0;
            g_m2[mlidx + 8] = m1; g_l2[mlidx + 8] = l1;
        }
    } else {
        float* st = (float*)sm;
        float inv0 = 1.f / l0, inv1 = 1.f / l1;
        #pragma unroll
        for (int nt = 0; nt < 8; nt++) {
            *(float2*)(st + r0 * 66 + 8 * nt + 2 * qd) =
                make_float2(oc[nt][0] * inv0, oc[nt][1] * inv0);
            *(float2*)(st + (r0 + 8) * 66 + 8 * nt + 2 * qd) =
                make_float2(oc[nt][2] * inv1, oc[nt][3] * inv1);
        }
        __syncthreads();
        float gamma = gp[0];
        int n0 = qt * 128;
        #pragma unroll 4
        for (int r2 = 0; r2 < 32; r2++) {
            int idx = r2 * 256 + tid;
            int c = idx >> 7, nl = idx & 127;
            size_t ga = ((size_t)b * 64 + c) * (size_t)N_ + n0 + nl;
            outg[ga] = gamma * st[nl * 66 + c] + xr[ga];
        }
    }
}

// ---------------- Launch ----------------

extern "C" void kernel_launch(void* const* d_in, const int* in_sizes, int n_in,
                              void* d_out, int out_size)
{
    (void)in_sizes; (void)n_in; (void)out_size;
    const float* x     = (const float*)d_in[0];
    const float* w_q   = (const float*)d_in[1];
    const float* b_q   = (const float*)d_in[2];
    const float* w_K   = (const float*)d_in[3];
    const float* b_K   = (const float*)d_in[4];
    const float* w_V   = (const float*)d_in[5];
    const float* b_V   = (const float*)d_in[6];
    const float* w_Q   = (const float*)d_in[7];
    const float* b_Q   = (const float*)d_in[8];
    const float* w_k   = (const float*)d_in[9];
    const float* b_k   = (const float*)d_in[10];
    const float* w_v   = (const float*)d_in[11];
    const float* b_v   = (const float*)d_in[12];
    const float* gamma = (const float*)d_in[13];
    float* out = (float*)d_out;

    const int attn_smem = 384 * PR * 4;   // 55296 B

    cudaFuncSetAttribute(projX_kernel, cudaFuncAttributeMaxDynamicSharedMemorySize, PROJX_SMEM);
    cudaFuncSetAttribute(projP_kernel, cudaFuncAttributeMaxDynamicSharedMemorySize, PROJP_SMEM);
    cudaFuncSetAttribute(projC_kernel, cudaFuncAttributeMaxDynamicSharedMemorySize, PROJC_SMEM);
    cudaFuncSetAttribute(attn_kernel<false>, cudaFuncAttributeMaxDynamicSharedMemorySize, attn_smem);
    cudaFuncSetAttribute(attn_kernel<true>,  cudaFuncAttributeMaxDynamicSharedMemorySize, attn_smem);

    // Projections (bf16 tensor-core), emitting attention-ready perm layouts.
    projX_kernel<<<dim3(B_*N_/128, 3), 256, PROJX_SMEM>>>(x, w_K, b_K, w_V, b_V, w_Q, b_Q);
    projP_kernel<<<B_*N4_/128, 256, PROJP_SMEM>>>(x, w_q, b_q);

    // Stage 1 attention: split-K over 4 parts (8 x 8 x 4 = 256 CTAs).
    attn_kernel<false><<<dim3(N4_/128, B_, SPLIT1), 256, attn_smem>>>(nullptr, nullptr, nullptr);

    // Stage 2 projections with fused split-K combine.
    projC_kernel<<<dim3(BN4/128, 2), 256, PROJC_SMEM>>>(w_k, b_k, w_v, b_v);

    // Stage 2 attention + residual epilogue (32 x 8 = 256 CTAs).
    attn_kernel<true><<<dim3(N_/128, B_), 256, attn_smem>>>(out, x, gamma);
}

// round 15
// speedup vs baseline: 7.5355x; 1.0250x over previous
#include <cuda_runtime.h>
#include <cstdint>
#include <cstddef>

#define B_  8
#define C_  64
#define N_  4096
#define N4_ 1024
#define SPLIT1 4
#define BN4 (B_*N4_)
#define PR 36
#define LOG2E 1.4426950408889634f

typedef unsigned long long u64;
typedef unsigned int u32;

// bf16 operands as bf16x2 words; per row 32 words over the 64-elt contraction
// dim, word w stored at perm p(w) = (w&3)*8 + (w>>2).
__device__ u32 g_K [B_*N_*32];          // (b,key)[32]     stage1 keys
__device__ u32 g_V [B_*C_*(N_/64)*32];  // (b,c,ktile)[32] stage1 values
__device__ u32 g_Q [B_*N_*32];          // (b,q)[32]       stage2 queries (pre-scaled by log2e)
__device__ u32 g_qp[B_*N4_*32];         // (b,j)[32]       stage1 pooled queries (pre-scaled)
__device__ u32 g_kp[B_*N4_*32];         // (b,j)[32]       stage2 keys
__device__ u32 g_vp[B_*C_*(N4_/64)*32]; // (b,c,ktile)[32] stage2 values
__device__ float g_po[SPLIT1*BN4*C_];   // split-K partials (unnormalized)
__device__ float g_m2[SPLIT1*BN4];
__device__ float g_l2[SPLIT1*BN4];

__device__ __forceinline__ u32 bf2(float lo, float hi) {
    u32 r; asm("cvt.rn.bf16x2.f32 %0, %1, %2;" : "=r"(r) : "f"(hi), "f"(lo)); return r;
}
__device__ __forceinline__ float ex2(float x) {
    float r; asm("ex2.approx.f32 %0, %1;" : "=f"(r) : "f"(x)); return r;
}
__device__ __forceinline__ int permw(int w) { return (w & 3) * 8 + (w >> 2); }

__device__ __forceinline__ void cpa16(u32* dst, const u32* src) {
    u32 d = (u32)__cvta_generic_to_shared(dst);
    asm volatile("cp.async.ca.shared.global [%0], [%1], 16;" :: "r"(d), "l"(src));
}
#define CP_COMMIT() asm volatile("cp.async.commit_group;" ::: "memory")
#define CP_WAIT0()  asm volatile("cp.async.wait_group 0;" ::: "memory")

__device__ __forceinline__ void mma_bf16(float c[4], u32 a0, u32 a1, u32 a2, u32 a3,
                                         u32 b0, u32 b1) {
    asm volatile(
        "mma.sync.aligned.m16n8k16.row.col.f32.bf16.bf16.f32 "
        "{%0,%1,%2,%3},{%4,%5,%6,%7},{%8,%9},{%0,%1,%2,%3};"
        : "+f"(c[0]), "+f"(c[1]), "+f"(c[2]), "+f"(c[3])
        : "r"(a0), "r"(a1), "r"(a2), "r"(a3), "r"(b0), "r"(b1));
}

// ================= bf16-MMA projection core ================================

__device__ __forceinline__ void stage_W(const float* __restrict__ w,
                                        const float* __restrict__ bias,
                                        u32* sW, float* sb, int tid, float scale)
{
    for (int i = tid; i < 1024; i += 256) {
        int o = i >> 4, t = i & 15;
        float4 v = *(const float4*)(w + o * 64 + 4 * t);
        sW[o * PR + permw(2 * t)]     = bf2(v.x * scale, v.y * scale);
        sW[o * PR + permw(2 * t + 1)] = bf2(v.z * scale, v.w * scale);
    }
    if (tid < 64) sb[tid] = bias[tid] * scale;
}

// MMA over rows r0, r0+8 of sX against all 64 couts of sW.
__device__ __forceinline__ void proj_mma(const u32* sX, const u32* sW,
                                         float sc[8][4], int r0, int grp, int qd)
{
    u32 a0[8], a1[8];
    #pragma unroll
    for (int u = 0; u < 2; u++) {
        uint4 x0 = *(const uint4*)(sX + r0 * PR + 8 * qd + 4 * u);
        uint4 x1 = *(const uint4*)(sX + (r0 + 8) * PR + 8 * qd + 4 * u);
        a0[4*u] = x0.x; a0[4*u+1] = x0.y; a0[4*u+2] = x0.z; a0[4*u+3] = x0.w;
        a1[4*u] = x1.x; a1[4*u+1] = x1.y; a1[4*u+2] = x1.z; a1[4*u+3] = x1.w;
    }
    #pragma unroll
    for (int nt = 0; nt < 8; nt++) {
        sc[nt][0] = 0.f; sc[nt][1] = 0.f; sc[nt][2] = 0.f; sc[nt][3] = 0.f;
        const u32* bp = sW + (8 * nt + grp) * PR + 8 * qd;
        uint4 B0 = *(const uint4*)bp;
        uint4 B1 = *(const uint4*)(bp + 4);
        mma_bf16(sc[nt], a0[0], a1[0], a0[1], a1[1], B0.x, B0.y);
        mma_bf16(sc[nt], a0[2], a1[2], a0[3], a1[3], B0.z, B0.w);
        mma_bf16(sc[nt], a0[4], a1[4], a0[5], a1[5], B1.x, B1.y);
        mma_bf16(sc[nt], a0[6], a1[6], a0[7], a1[7], B1.z, B1.w);
    }
}

__device__ __forceinline__ void store_nmaj(u32* __restrict__ dst,
                                           const float sc[8][4], const float* sb,
                                           int r0, int qd)
{
    u32 w0[8], w1[8];
    #pragma unroll
    for (int nt = 0; nt < 8; nt++) {
        float2 bb = *(const float2*)(sb + 8 * nt + 2 * qd);
        w0[nt] = bf2(sc[nt][0] + bb.x, sc[nt][1] + bb.y);
        w1[nt] = bf2(sc[nt][2] + bb.x, sc[nt][3] + bb.y);
    }
    *(uint4*)(dst + (size_t)r0 * 32 + 8 * qd)     = make_uint4(w0[0], w0[1], w0[2], w0[3]);
    *(uint4*)(dst + (size_t)r0 * 32 + 8 * qd + 4) = make_uint4(w0[4], w0[5], w0[6], w0[7]);
    *(uint4*)(dst + (size_t)(r0 + 8) * 32 + 8 * qd)     = make_uint4(w1[0], w1[1], w1[2], w1[3]);
    *(uint4*)(dst + (size_t)(r0 + 8) * 32 + 8 * qd + 4) = make_uint4(w1[4], w1[5], w1[6], w1[7]);
}

// c-major perm store (V, 128 positions): transpose via fp32 st [128 pos][67].
__device__ __forceinline__ void store_cmaj128(u32* __restrict__ out, int NT, int ktbase,
                                              float* st, const float sc[8][4],
                                              const float* sb, int r0, int qd, int tid)
{
    __syncthreads();
    #pragma unroll
    for (int nt = 0; nt < 8; nt++) {
        float2 bb = *(const float2*)(sb + 8 * nt + 2 * qd);
        st[r0 * 67 + 8 * nt + 2 * qd]     = sc[nt][0] + bb.x;
        st[r0 * 67 + 8 * nt + 2 * qd + 1] = sc[nt][1] + bb.y;
        st[(r0 + 8) * 67 + 8 * nt + 2 * qd]     = sc[nt][2] + bb.x;
        st[(r0 + 8) * 67 + 8 * nt + 2 * qd + 1] = sc[nt][3] + bb.y;
    }
    __syncthreads();
    for (int i = tid; i < 4096; i += 256) {
        int w = i & 31, tile = (i >> 5) & 1, cout = i >> 6;
        float v0 = st[(tile * 64 + 2 * w) * 67 + cout];
        float v1 = st[(tile * 64 + 2 * w + 1) * 67 + cout];
        out[((size_t)cout * NT + ktbase + tile) * 32 + permw(w)] = bf2(v0, v1);
    }
}

// ---- K / V / Q / pooled-q projections from x ----
// blockIdx.y: 0=K 1=V 2=Q (128-pos tiles, grid.x=256)  3=pooled q (grid.x<64)
#define PROJX_SMEM ((128*67 + 64) * 4)
__global__ __launch_bounds__(256)
void projX_kernel(const float* __restrict__ x,
                  const float* __restrict__ wK, const float* __restrict__ bK,
                  const float* __restrict__ wV, const float* __restrict__ bV,
                  const float* __restrict__ wQ, const float* __restrict__ bQ,
                  const float* __restrict__ wq, const float* __restrict__ bq)
{
    int which = blockIdx.y;
    if (which == 3 && blockIdx.x >= B_*N4_/128) return;

    extern __shared__ u32 sm[];
    u32* sX = sm;                       // 128*36
    u32* sW = sm + 128 * PR;            // 64*36
    float* st = (float*)sm;             // 128*67 (post-mma, V only)
    float* sb = (float*)(sm + 128 * 67);
    int tid = threadIdx.x;
    const float* w  = which == 0 ? wK : (which == 1 ? wV : (which == 2 ? wQ : wq));
    const float* bs = which == 0 ? bK : (which == 1 ? bV : (which == 2 ? bQ : bq));
    stage_W(w, bs, sW, sb, tid, which >= 2 ? LOG2E : 1.0f);

    if (which != 3) {
        int gpos0 = blockIdx.x * 128;
        int b = gpos0 >> 12, n0 = gpos0 & (N_ - 1);
        const float* xb = x + (size_t)b * C_ * N_ + n0;
        #pragma unroll
        for (int it = 0; it < 2; it++) {
            int idx = it * 256 + tid;
            int pos = idx & 127, a = idx >> 7;
            u32 wb[8];
            #pragma unroll
            for (int j = 0; j < 8; j++) {
                int ch = 8 * j + 2 * a;
                wb[j] = bf2(xb[(size_t)ch * N_ + pos], xb[(size_t)(ch + 1) * N_ + pos]);
            }
            *(uint4*)(sX + pos * PR + 8 * a)     = make_uint4(wb[0], wb[1], wb[2], wb[3]);
            *(uint4*)(sX + pos * PR + 8 * a + 4) = make_uint4(wb[4], wb[5], wb[6], wb[7]);
        }
        __syncthreads();

        int wid = tid >> 5, lane = tid & 31, grp = lane >> 2, qd = lane & 3;
        int r0 = wid * 16 + grp;
        float sc[8][4];
        proj_mma(sX, sW, sc, r0, grp, qd);
        if (which == 0)      store_nmaj(g_K + (size_t)gpos0 * 32, sc, sb, r0, qd);
        else if (which == 2) store_nmaj(g_Q + (size_t)gpos0 * 32, sc, sb, r0, qd);
        else store_cmaj128(g_V + (size_t)b * 64 * 64 * 32, 64, n0 >> 6, st, sc, sb, r0, qd, tid);
    } else {
        // Pooled q (pool commutes with 1x1 conv); log2e folded into W.
        int gpos0 = blockIdx.x * 128;
        int b = gpos0 >> 10, j0 = gpos0 & (N4_ - 1);
        const float* xb = x + (size_t)b * C_ * N_;
        #pragma unroll
        for (int it = 0; it < 2; it++) {
            int idx = it * 256 + tid;
            int pos = idx & 127, a = idx >> 7;
            int jj = j0 + pos;
            size_t base = (size_t)(jj >> 5) * 128 + (jj & 31) * 2;
            u32 wb[8];
            #pragma unroll
            for (int j = 0; j < 8; j++) {
                int ch = 8 * j + 2 * a;
                const float* p0 = xb + (size_t)ch * N_ + base;
                const float* p1 = xb + (size_t)(ch + 1) * N_ + base;
                float v0 = 0.25f * (p0[0] + p0[1] + p0[64] + p0[65]);
                float v1 = 0.25f * (p1[0] + p1[1] + p1[64] + p1[65]);
                wb[j] = bf2(v0, v1);
            }
            *(uint4*)(sX + pos * PR + 8 * a)     = make_uint4(wb[0], wb[1], wb[2], wb[3]);
            *(uint4*)(sX + pos * PR + 8 * a + 4) = make_uint4(wb[4], wb[5], wb[6], wb[7]);
        }
        __syncthreads();

        int wid = tid >> 5, lane = tid & 31, grp = lane >> 2, qd = lane & 3;
        int r0 = wid * 16 + grp;
        float sc[8][4];
        proj_mma(sX, sW, sc, r0, grp, qd);
        store_nmaj(g_qp + (size_t)gpos0 * 32, sc, sb, r0, qd);
    }
}

// ---- kp + vp projection with ONE fused split-K combine per CTA ----
// CTA = 64 positions (grid 128). Warps 0-3: kp MMA; warps 4-7: vp MMA.
#define PC_SX   0                       // 64*36 words
#define PC_SWK  (64*PR)                 // 64*36
#define PC_SWV  (PC_SWK + 64*PR)        // 64*36
#define PC_ST   (PC_SWV + 64*PR)        // 64*67 floats
#define PC_SB   (PC_ST + 64*67)         // 128 floats (bk | bv)
#define PC_SWT  (PC_SB + 128)           // 64*4 floats
#define PROJC_SMEM ((PC_SWT + 256) * 4)
__global__ __launch_bounds__(256)
void projC_kernel(const float* __restrict__ wk, const float* __restrict__ bk,
                  const float* __restrict__ wv, const float* __restrict__ bv)
{
    extern __shared__ u32 sm[];
    u32* sX  = sm + PC_SX;
    u32* sWk = sm + PC_SWK;
    u32* sWv = sm + PC_SWV;
    float* st  = (float*)(sm + PC_ST);
    float* sb  = (float*)(sm + PC_SB);
    float* swt = (float*)(sm + PC_SWT);
    int tid = threadIdx.x;
    stage_W(wk, bk, sWk, sb, tid, 1.0f);
    stage_W(wv, bv, sWv, sb + 64, tid, 1.0f);

    int gpos0 = blockIdx.x * 64;
    int b = gpos0 >> 10, j0 = gpos0 & (N4_ - 1);

    // Per-position combine weights (inv folded in).
    if (tid < 64) {
        int grow = gpos0 + tid;
        float mv[SPLIT1], lv[SPLIT1], M = -1e30f;
        #pragma unroll
        for (int p = 0; p < SPLIT1; p++) {
            mv[p] = g_m2[p * BN4 + grow];
            lv[p] = g_l2[p * BN4 + grow];
            M = fmaxf(M, mv[p]);
        }
        float wv_[SPLIT1], ls = 0.f;
        #pragma unroll
        for (int p = 0; p < SPLIT1; p++) { wv_[p] = ex2(mv[p] - M); ls += lv[p] * wv_[p]; }
        float inv = 1.f / ls;
        #pragma unroll
        for (int p = 0; p < SPLIT1; p++) swt[tid * 4 + p] = wv_[p] * inv;
    }
    __syncthreads();

    // Combine partials ONCE, write bf16 perm sX directly.
    for (int i = tid; i < 1024; i += 256) {
        int c4 = i & 15, pos = i >> 4;
        const float* wp = swt + pos * 4;
        float4 acc = make_float4(0.f, 0.f, 0.f, 0.f);
        #pragma unroll
        for (int p = 0; p < SPLIT1; p++) {
            float4 a = *(const float4*)(g_po + ((size_t)p * BN4 + gpos0 + pos) * 64 + 4 * c4);
            float wf = wp[p];
            acc.x += wf * a.x; acc.y += wf * a.y; acc.z += wf * a.z; acc.w += wf * a.w;
        }
        sX[pos * PR + permw(2 * c4)]     = bf2(acc.x, acc.y);
        sX[pos * PR + permw(2 * c4 + 1)] = bf2(acc.z, acc.w);
    }
    __syncthreads();

    int wid = tid >> 5, lane = tid & 31, grp = lane >> 2, qd = lane & 3;
    int half = wid >> 2;                 // 0 = kp, 1 = vp
    int r0 = (wid & 3) * 16 + grp;       // rows within 64-pos tile
    float sc[8][4];
    proj_mma(sX, half ? sWv : sWk, sc, r0, grp, qd);

    if (half == 0) {
        store_nmaj(g_kp + (size_t)gpos0 * 32, sc, sb, r0, qd);
    } else {
        #pragma unroll
        for (int nt = 0; nt < 8; nt++) {
            float2 bb = *(const float2*)(sb + 64 + 8 * nt + 2 * qd);
            st[r0 * 67 + 8 * nt + 2 * qd]     = sc[nt][0] + bb.x;
            st[r0 * 67 + 8 * nt + 2 * qd + 1] = sc[nt][1] + bb.y;
            st[(r0 + 8) * 67 + 8 * nt + 2 * qd]     = sc[nt][2] + bb.x;
            st[(r0 + 8) * 67 + 8 * nt + 2 * qd + 1] = sc[nt][3] + bb.y;
        }
    }
    __syncthreads();

    // vp transpose scatter: one ktile (64 positions) per CTA.
    u32* out = g_vp + (size_t)b * 64 * 16 * 32;
    int ktb = j0 >> 6;
    for (int i = tid; i < 2048; i += 256) {
        int w = i & 31, cout = i >> 5;
        float v0 = st[(2 * w) * 67 + cout];
        float v1 = st[(2 * w + 1) * 67 + cout];
        out[((size_t)cout * 16 + ktb) * 32 + permw(w)] = bf2(v0, v1);
    }
}

// ================= bf16 m16n8k16 flash attention (unchanged R14 core) ======
template<bool FINAL>
__global__ __launch_bounds__(256, 2)
void attn_kernel(float* __restrict__ outg,
                 const float* __restrict__ xr,
                 const float* __restrict__ gp)
{
    constexpr int NKEY = FINAL ? 1024 : 4096;
    constexpr int NQ   = FINAL ? 4096 : 1024;
    constexpr int NT   = NKEY / 64;

    extern __shared__ u32 sm[];
    u32* sQ  = sm;                 // 128*36
    u32* sK0 = sQ  + 128 * PR;     // 64*36
    u32* sV0 = sK0 + 64 * PR;
    u32* sK1 = sV0 + 64 * PR;
    u32* sV1 = sK1 + 64 * PR;      // total 384*36 words

    int tid = threadIdx.x;
    int wid = tid >> 5, lane = tid & 31;
    int grp = lane >> 2, qd = lane & 3;
    int b = blockIdx.y, qt = blockIdx.x;
    int part = FINAL ? 0 : blockIdx.z;

    const u32* Qg = (FINAL ? g_Q  : g_qp) + ((size_t)b * NQ + qt * 128) * 32;
    const u32* Kg = (FINAL ? g_kp : g_K ) + (size_t)b * NKEY * 32;
    const u32* Vg = (FINAL ? g_vp : g_V ) + (size_t)b * C_ * NT * 32;

    int nkt = FINAL ? NT : NT / SPLIT1;
    int kt0 = part * nkt;

    #pragma unroll
    for (int r = 0; r < 4; r++) {
        int idx = r * 256 + tid;
        int row = idx >> 3, q4 = (idx & 7) * 4;
        *(uint4*)(sQ + row * PR + q4) = *(const uint4*)(Qg + (size_t)row * 32 + q4);
    }
    #pragma unroll
    for (int r = 0; r < 2; r++) {
        int idx = r * 256 + tid;
        int row = idx >> 3, q4 = (idx & 7) * 4;
        *(uint4*)(sK0 + row * PR + q4) =
            *(const uint4*)(Kg + ((size_t)kt0 * 64 + row) * 32 + q4);
        *(uint4*)(sV0 + row * PR + q4) =
            *(const uint4*)(Vg + ((size_t)row * NT + kt0) * 32 + q4);
    }
    __syncthreads();

    int r0 = wid * 16 + grp;
    u32 aQ0[8], aQ1[8];
    #pragma unroll
    for (int u = 0; u < 2; u++) {
        uint4 x0 = *(const uint4*)(sQ + r0 * PR + 8 * qd + 4 * u);
        uint4 x1 = *(const uint4*)(sQ + (r0 + 8) * PR + 8 * qd + 4 * u);
        aQ0[4*u] = x0.x; aQ0[4*u+1] = x0.y; aQ0[4*u+2] = x0.z; aQ0[4*u+3] = x0.w;
        aQ1[4*u] = x1.x; aQ1[4*u+1] = x1.y; aQ1[4*u+2] = x1.z; aQ1[4*u+3] = x1.w;
    }

    float m0 = -1e30f, m1 = -1e30f, l0 = 0.f, l1 = 0.f;
    float oc[8][4];
    #pragma unroll
    for (int nt = 0; nt < 8; nt++) {
        oc[nt][0] = 0.f; oc[nt][1] = 0.f; oc[nt][2] = 0.f; oc[nt][3] = 0.f;
    }

    for (int kk = 0; kk < nkt; kk++) {
        const u32* sKc = (kk & 1) ? sK1 : sK0;
        const u32* sVc = (kk & 1) ? sV1 : sV0;
        u32* sKn = (kk & 1) ? sK0 : sK1;
        u32* sVn = (kk & 1) ? sV0 : sV1;

        bool hasNext = (kk + 1 < nkt);
        if (hasNext) {
            int kt = kt0 + kk + 1;
            #pragma unroll
            for (int r = 0; r < 2; r++) {
                int idx = r * 256 + tid;
                int row = idx >> 3, q4 = (idx & 7) * 4;
                cpa16(sKn + row * PR + q4, Kg + ((size_t)kt * 64 + row) * 32 + q4);
                cpa16(sVn + row * PR + q4, Vg + ((size_t)row * NT + kt) * 32 + q4);
            }
            CP_COMMIT();
        }

        // S = Q K^T (log2 domain).
        float sc[8][4];
        #pragma unroll
        for (int nt = 0; nt < 8; nt++) {
            sc[nt][0] = 0.f; sc[nt][1] = 0.f; sc[nt][2] = 0.f; sc[nt][3] = 0.f;
            const u32* bp = sKc + (8 * nt + grp) * PR + 8 * qd;
            uint4 B0 = *(const uint4*)bp;
            uint4 B1 = *(const uint4*)(bp + 4);
            mma_bf16(sc[nt], aQ0[0], aQ1[0], aQ0[1], aQ1[1], B0.x, B0.y);
            mma_bf16(sc[nt], aQ0[2], aQ1[2], aQ0[3], aQ1[3], B0.z, B0.w);
            mma_bf16(sc[nt], aQ0[4], aQ1[4], aQ0[5], aQ1[5], B1.x, B1.y);
            mma_bf16(sc[nt], aQ0[6], aQ1[6], aQ0[7], aQ1[7], B1.z, B1.w);
        }

        // Online softmax; p = exp2(s - m) directly.
        float rx0 = -1e30f, rx1 = -1e30f;
        #pragma unroll
        for (int nt = 0; nt < 8; nt++) {
            rx0 = fmaxf(rx0, fmaxf(sc[nt][0], sc[nt][1]));
            rx1 = fmaxf(rx1, fmaxf(sc[nt][2], sc[nt][3]));
        }
        rx0 = fmaxf(rx0, __shfl_xor_sync(0xffffffffu, rx0, 1));
        rx0 = fmaxf(rx0, __shfl_xor_sync(0xffffffffu, rx0, 2));
        rx1 = fmaxf(rx1, __shfl_xor_sync(0xffffffffu, rx1, 1));
        rx1 = fmaxf(rx1, __shfl_xor_sync(0xffffffffu, rx1, 2));
        float mn0 = fmaxf(m0, rx0), mn1 = fmaxf(m1, rx1);
        float al0 = ex2(m0 - mn0), al1 = ex2(m1 - mn1);
        m0 = mn0; m1 = mn1;

        u32 prow0[8], prow1[8];
        float sum0 = 0.f, sum1 = 0.f;
        #pragma unroll
        for (int nt = 0; nt < 8; nt++) {
            float p00 = ex2(sc[nt][0] - mn0);
            float p01 = ex2(sc[nt][1] - mn0);
            float p10 = ex2(sc[nt][2] - mn1);
            float p11 = ex2(sc[nt][3] - mn1);
            sum0 += p00 + p01; sum1 += p10 + p11;
            prow0[nt] = bf2(p00, p01);
            prow1[nt] = bf2(p10, p11);
        }
        sum0 += __shfl_xor_sync(0xffffffffu, sum0, 1);
        sum0 += __shfl_xor_sync(0xffffffffu, sum0, 2);
        sum1 += __shfl_xor_sync(0xffffffffu, sum1, 1);
        sum1 += __shfl_xor_sync(0xffffffffu, sum1, 2);
        l0 = l0 * al0 + sum0;
        l1 = l1 * al1 + sum1;
        #pragma unroll
        for (int nt = 0; nt < 8; nt++) {
            oc[nt][0] *= al0; oc[nt][1] *= al0;
            oc[nt][2] *= al1; oc[nt][3] *= al1;
        }

        // PV: A-frags are prow0/prow1 directly (same thread-data mapping).
        #pragma unroll
        for (int nt = 0; nt < 8; nt++) {
            const u32* bp = sVc + (8 * nt + grp) * PR + 8 * qd;
            uint4 B0 = *(const uint4*)bp;
            uint4 B1 = *(const uint4*)(bp + 4);
            mma_bf16(oc[nt], prow0[0], prow1[0], prow0[1], prow1[1], B0.x, B0.y);
            mma_bf16(oc[nt], prow0[2], prow1[2], prow0[3], prow1[3], B0.z, B0.w);
            mma_bf16(oc[nt], prow0[4], prow1[4], prow0[5], prow1[5], B1.x, B1.y);
            mma_bf16(oc[nt], prow0[6], prow1[6], prow0[7], prow1[7], B1.z, B1.w);
        }

        if (hasNext) CP_WAIT0();
        __syncthreads();
    }

    if (!FINAL) {
        size_t mlidx = (size_t)(part * B_ + b) * N4_ + qt * 128 + r0;
        #pragma unroll
        for (int nt = 0; nt < 8; nt++) {
            *(float2*)(g_po + mlidx * 64 + 8 * nt + 2 * qd) =
                make_float2(oc[nt][0], oc[nt][1]);
            *(float2*)(g_po + (mlidx + 8) * 64 + 8 * nt + 2 * qd) =
                make_float2(oc[nt][2], oc[nt][3]);
        }
        if (qd == 0) {
            g_m2[mlidx] = m0; g_l2[mlidx] = l0;
            g_m2[mlidx + 8] = m1; g_l2[mlidx + 8] = l1;
        }
    } else {
        float* st = (float*)sm;
        float inv0 = 1.f / l0, inv1 = 1.f / l1;
        #pragma unroll
        for (int nt = 0; nt < 8; nt++) {
            *(float2*)(st + r0 * 66 + 8 * nt + 2 * qd) =
                make_float2(oc[nt][0] * inv0, oc[nt][1] * inv0);
            *(float2*)(st + (r0 + 8) * 66 + 8 * nt + 2 * qd) =
                make_float2(oc[nt][2] * inv1, oc[nt][3] * inv1);
        }
        __syncthreads();
        float gamma = gp[0];
        int n0 = qt * 128;
        #pragma unroll 4
        for (int r2 = 0; r2 < 32; r2++) {
            int idx = r2 * 256 + tid;
            int c = idx >> 7, nl = idx & 127;
            size_t ga = ((size_t)b * 64 + c) * (size_t)N_ + n0 + nl;
            outg[ga] = gamma * st[nl * 66 + c] + xr[ga];
        }
    }
}

// ---------------- Launch ----------------

extern "C" void kernel_launch(void* const* d_in, const int* in_sizes, int n_in,
                              void* d_out, int out_size)
{
    (void)in_sizes; (void)n_in; (void)out_size;
    const float* x     = (const float*)d_in[0];
    const float* w_q   = (const float*)d_in[1];
    const float* b_q   = (const float*)d_in[2];
    const float* w_K   = (const float*)d_in[3];
    const float* b_K   = (const float*)d_in[4];
    const float* w_V   = (const float*)d_in[5];
    const float* b_V   = (const float*)d_in[6];
    const float* w_Q   = (const float*)d_in[7];
    const float* b_Q   = (const float*)d_in[8];
    const float* w_k   = (const float*)d_in[9];
    const float* b_k   = (const float*)d_in[10];
    const float* w_v   = (const float*)d_in[11];
    const float* b_v   = (const float*)d_in[12];
    const float* gamma = (const float*)d_in[13];
    float* out = (float*)d_out;

    const int attn_smem = 384 * PR * 4;   // 55296 B

    cudaFuncSetAttribute(projX_kernel, cudaFuncAttributeMaxDynamicSharedMemorySize, PROJX_SMEM);
    cudaFuncSetAttribute(projC_kernel, cudaFuncAttributeMaxDynamicSharedMemorySize, PROJC_SMEM);
    cudaFuncSetAttribute(attn_kernel<false>, cudaFuncAttributeMaxDynamicSharedMemorySize, attn_smem);
    cudaFuncSetAttribute(attn_kernel<true>,  cudaFuncAttributeMaxDynamicSharedMemorySize, attn_smem);

    // All stage-1 projections + pooled q in ONE launch (y: 0=K 1=V 2=Q 3=qp).
    projX_kernel<<<dim3(B_*N_/128, 4), 256, PROJX_SMEM>>>(
        x, w_K, b_K, w_V, b_V, w_Q, b_Q, w_q, b_q);

    // Stage 1 attention: split-K over 4 parts (8 x 8 x 4 = 256 CTAs).
    attn_kernel<false><<<dim3(N4_/128, B_, SPLIT1), 256, attn_smem>>>(nullptr, nullptr, nullptr);

    // Stage 2 projections: single fused combine + kp/vp MMAs (128 CTAs).
    projC_kernel<<<BN4/64, 256, PROJC_SMEM>>>(w_k, b_k, w_v, b_v);

    // Stage 2 attention + residual epilogue (32 x 8 = 256 CTAs).
    attn_kernel<true><<<dim3(N_/128, B_), 256, attn_smem>>>(out, x, gamma);
}